// round 8
// baseline (speedup 1.0000x reference)
#include <cuda_runtime.h>
#include <cuda_bf16.h>
#include <cstdint>

// Problem constants
#define T_LEN   1024
#define BSZ     4
#define EMBED   1024
#define NHEADS  16
#define HDIM    64
#define NBH     (BSZ * NHEADS)      // 64
#define MROWS   (T_LEN * BSZ)       // 4096
#define SCALING 0.125f

// bf16 hi/lo scratch (q scaled)
__device__ __nv_bfloat16 g_qh[NBH * T_LEN * HDIM];
__device__ __nv_bfloat16 g_ql[NBH * T_LEN * HDIM];
__device__ __nv_bfloat16 g_kh[NBH * T_LEN * HDIM];
__device__ __nv_bfloat16 g_kl[NBH * T_LEN * HDIM];
__device__ __nv_bfloat16 g_vh[NBH * T_LEN * HDIM];
__device__ __nv_bfloat16 g_vl[NBH * T_LEN * HDIM];
__device__ __nv_bfloat16 g_attnh[MROWS * EMBED];
__device__ __nv_bfloat16 g_attnl[MROWS * EMBED];
// bf16 split GEMM operands
__device__ __nv_bfloat16 g_Ah[MROWS * EMBED];
__device__ __nv_bfloat16 g_Al[MROWS * EMBED];
__device__ __nv_bfloat16 g_Bh[3 * EMBED * EMBED];
__device__ __nv_bfloat16 g_Bl[3 * EMBED * EMBED];

// ---------------------------------------------------------------------------
// PTX helpers
// ---------------------------------------------------------------------------
__device__ __forceinline__ uint32_t s2u(const void* p) {
    return (uint32_t)__cvta_generic_to_shared(p);
}
__device__ __forceinline__ void cp_async16(uint32_t dst, const void* src) {
    asm volatile("cp.async.cg.shared.global [%0], [%1], 16;\n" :: "r"(dst), "l"(src));
}
__device__ __forceinline__ void cp_commit() {
    asm volatile("cp.async.commit_group;\n");
}
template<int N>
__device__ __forceinline__ void cp_wait() {
    asm volatile("cp.async.wait_group %0;\n" :: "n"(N));
}
__device__ __forceinline__ void ldm_x4(uint32_t* r, uint32_t addr) {
    asm volatile("ldmatrix.sync.aligned.m8n8.x4.shared.b16 {%0,%1,%2,%3}, [%4];"
                 : "=r"(r[0]), "=r"(r[1]), "=r"(r[2]), "=r"(r[3]) : "r"(addr));
}
__device__ __forceinline__ void ldm_x4_trans(uint32_t* r, uint32_t addr) {
    asm volatile("ldmatrix.sync.aligned.m8n8.x4.trans.shared.b16 {%0,%1,%2,%3}, [%4];"
                 : "=r"(r[0]), "=r"(r[1]), "=r"(r[2]), "=r"(r[3]) : "r"(addr));
}
__device__ __forceinline__ void mma16816(float* c, const uint32_t* a, const uint32_t* b) {
    asm volatile("mma.sync.aligned.m16n8k16.row.col.f32.bf16.bf16.f32 "
                 "{%0,%1,%2,%3}, {%4,%5,%6,%7}, {%8,%9}, {%0,%1,%2,%3};"
                 : "+f"(c[0]), "+f"(c[1]), "+f"(c[2]), "+f"(c[3])
                 : "r"(a[0]), "r"(a[1]), "r"(a[2]), "r"(a[3]), "r"(b[0]), "r"(b[1]));
}
__device__ __host__ __forceinline__ uint32_t sw128(uint32_t off) {
    return off ^ ((off >> 3) & 0x70);
}
__device__ __forceinline__ uint32_t pack_hi2(float a, float b) {
    __nv_bfloat162 t; t.x = __float2bfloat16(a); t.y = __float2bfloat16(b);
    uint32_t r; memcpy(&r, &t, 4); return r;
}
__device__ __forceinline__ uint32_t pack_lo2(float a, float b) {
    __nv_bfloat16 ha = __float2bfloat16(a), hb = __float2bfloat16(b);
    __nv_bfloat162 t;
    t.x = __float2bfloat16(a - __bfloat162float(ha));
    t.y = __float2bfloat16(b - __bfloat162float(hb));
    uint32_t r; memcpy(&r, &t, 4); return r;
}

// ---------------------------------------------------------------------------
// fp32 -> (hi, lo) bf16 split
// ---------------------------------------------------------------------------
__global__ __launch_bounds__(256)
void split_kernel(const float* __restrict__ src, __nv_bfloat16* __restrict__ hi,
                  __nv_bfloat16* __restrict__ lo, int n4)
{
    int i = blockIdx.x * 256 + threadIdx.x;
    if (i >= n4) return;
    float4 v = reinterpret_cast<const float4*>(src)[i];
    reinterpret_cast<uint32_t*>(hi)[2 * i]     = pack_hi2(v.x, v.y);
    reinterpret_cast<uint32_t*>(hi)[2 * i + 1] = pack_hi2(v.z, v.w);
    reinterpret_cast<uint32_t*>(lo)[2 * i]     = pack_lo2(v.x, v.y);
    reinterpret_cast<uint32_t*>(lo)[2 * i + 1] = pack_lo2(v.z, v.w);
}

// ---------------------------------------------------------------------------
// mma.sync split-bf16 GEMM — R6 2-stage structure + x4 B-frag loads
// ---------------------------------------------------------------------------
#define GK 1024
#define TM 128
#define TN 128
#define TBK 32
#define NKS (GK / TBK)
#define A_ST 40
#define TILE_B (128 * A_ST * 2)
#define STAGE_B (4 * TILE_B)
#define GEMM_SMEM (2 * STAGE_B)   // 81920 -> 2 CTAs/SM

__device__ __forceinline__ void load_stage(uint32_t sbase,
    const __nv_bfloat16* __restrict__ Ah, const __nv_bfloat16* __restrict__ Al,
    const __nv_bfloat16* __restrict__ Bh, const __nv_bfloat16* __restrict__ Bl,
    int row0, int col0, int k0, int tid)
{
#pragma unroll
    for (int it = 0; it < 2; it++) {
        int idx = it * 256 + tid;
        int r = idx >> 2, c = idx & 3;
        uint32_t so = r * (A_ST * 2) + c * 16;
        size_t ga = (size_t)(row0 + r) * GK + k0 + c * 8;
        size_t gb = (size_t)(col0 + r) * GK + k0 + c * 8;
        cp_async16(sbase + 0 * TILE_B + so, Ah + ga);
        cp_async16(sbase + 1 * TILE_B + so, Al + ga);
        cp_async16(sbase + 2 * TILE_B + so, Bh + gb);
        cp_async16(sbase + 3 * TILE_B + so, Bl + gb);
    }
}

__global__ __launch_bounds__(256)
void gemm_mma(const __nv_bfloat16* __restrict__ Ah, const __nv_bfloat16* __restrict__ Al,
              const __nv_bfloat16* __restrict__ Bh, const __nv_bfloat16* __restrict__ Bl,
              const float* __restrict__ bias, int mode, float* __restrict__ out)
{
    extern __shared__ char smc[];
    const uint32_t sb = s2u(smc);
    const int tid  = threadIdx.x;
    const int lane = tid & 31;
    const int wid  = tid >> 5;
    const int wr = wid & 1;
    const int wc = wid >> 1;
    const int row0 = blockIdx.y * TM, col0 = blockIdx.x * TN;

    const int a_row = lane & 15;
    const int a_k8  = (lane >> 4) * 8;
    // x4 B-frag addressing (verified in R7: identical rel_err)
    const int b_mat = lane >> 3;
    const int b_nf_off = b_mat >> 1;
    const int b_k8  = (b_mat & 1) * 8;
    const int b_row = lane & 7;

    float acc[4][4][4];
#pragma unroll
    for (int i = 0; i < 4; i++)
#pragma unroll
        for (int j = 0; j < 4; j++)
#pragma unroll
            for (int q = 0; q < 4; q++) acc[i][j][q] = 0.f;

    load_stage(sb, Ah, Al, Bh, Bl, row0, col0, 0, tid);
    cp_commit();

    for (int ks = 0; ks < NKS; ks++) {
        const uint32_t cur = sb + (uint32_t)(ks & 1) * STAGE_B;
        if (ks + 1 < NKS) {
            load_stage(sb + (uint32_t)((ks + 1) & 1) * STAGE_B,
                       Ah, Al, Bh, Bl, row0, col0, (ks + 1) * TBK, tid);
            cp_commit();
            cp_wait<1>();
        } else {
            cp_wait<0>();
        }
        __syncthreads();

#pragma unroll
        for (int kk = 0; kk < 2; kk++) {
            const int k0 = kk * 16;
            uint32_t afh[4][4], afl[4][4];
#pragma unroll
            for (int mf = 0; mf < 4; mf++) {
                uint32_t aoff = (uint32_t)((wr * 64 + mf * 16 + a_row) * A_ST + k0 + a_k8) * 2;
                ldm_x4(afh[mf], cur + 0 * TILE_B + aoff);
                ldm_x4(afl[mf], cur + 1 * TILE_B + aoff);
            }
            uint32_t bfh[2][4], bfl[2][4];
#pragma unroll
            for (int nfp = 0; nfp < 2; nfp++) {
                uint32_t boff = (uint32_t)((wc * 32 + (2 * nfp + b_nf_off) * 8 + b_row) * A_ST
                                           + k0 + b_k8) * 2;
                ldm_x4(bfh[nfp], cur + 2 * TILE_B + boff);
                ldm_x4(bfl[nfp], cur + 3 * TILE_B + boff);
            }
#pragma unroll
            for (int mf = 0; mf < 4; mf++)
#pragma unroll
                for (int nfp = 0; nfp < 2; nfp++)
#pragma unroll
                    for (int half = 0; half < 2; half++) {
                        const int nf = 2 * nfp + half;
                        mma16816(acc[mf][nf], afh[mf], bfh[nfp] + half * 2);
                        mma16816(acc[mf][nf], afh[mf], bfl[nfp] + half * 2);
                        mma16816(acc[mf][nf], afl[mf], bfh[nfp] + half * 2);
                    }
        }
        __syncthreads();
    }

    const int g = lane >> 2, tig = lane & 3;
#pragma unroll
    for (int nf = 0; nf < 4; nf++) {
        const int e = col0 + wc * 32 + nf * 8 + tig * 2;
        const float bz0 = __ldg(bias + e);
        const float bz1 = __ldg(bias + e + 1);
#pragma unroll
        for (int mf = 0; mf < 4; mf++) {
#pragma unroll
            for (int half = 0; half < 2; half++) {
                const int m = row0 + wr * 64 + mf * 16 + g + half * 8;
                float v0 = acc[mf][nf][half * 2 + 0] + bz0;
                float v1 = acc[mf][nf][half * 2 + 1] + bz1;
                if (mode == 0) {
                    const int t = m >> 2, b = m & 3;
                    const int which = e >> 10;
                    const int rem = e & 1023;
                    const int h = rem >> 6, d = rem & 63;
                    const int n = (b << 4) + h;
                    if (which == 0) { v0 *= SCALING; v1 *= SCALING; }
                    __nv_bfloat16* dh = (which == 0) ? g_qh : (which == 1) ? g_kh : g_vh;
                    __nv_bfloat16* dl = (which == 0) ? g_ql : (which == 1) ? g_kl : g_vl;
                    size_t off = ((size_t)n << 16) + ((size_t)t << 6) + d;
                    *reinterpret_cast<uint32_t*>(dh + off) = pack_hi2(v0, v1);
                    *reinterpret_cast<uint32_t*>(dl + off) = pack_lo2(v0, v1);
                } else {
                    *reinterpret_cast<float2*>(out + (size_t)m * EMBED + e)
                        = make_float2(v0, v1);
                }
            }
        }
    }
}

// ---------------------------------------------------------------------------
// Flash attention — R6 structure (S -> softmax -> PV), x4 ldmatrix loads.
// CTA = 128 query rows x head n; 8 warps; key blocks of 64; 2 smem stages.
// ---------------------------------------------------------------------------
#define ABT 128
#define ABS 64
#define NBLK (T_LEN / ABS)   // 16
#define AQ_H   0
#define AQ_L   16384
#define AST0   32768
#define S_KH    0
#define S_KL    8192
#define S_VH    16384
#define S_VL    24576
#define S_BIAS  32768
#define BIAS_ST 68
#define S_KPM   (32768 + 128 * BIAS_ST * 4)   // 67584
#define AST_STRIDE (S_KPM + 256)              // 67840
#define ATTN_SMEM (AST0 + 2 * AST_STRIDE)     // 168448

__global__ __launch_bounds__(256, 1)
void attn_mma_kernel(const int*   __restrict__ kpm,
                     const float* __restrict__ attn_mask,
                     const float* __restrict__ attn_bias)
{
    extern __shared__ char smc[];
    const uint32_t sb = s2u(smc);
    const int tid = threadIdx.x, lane = tid & 31, wid = tid >> 5;
    const int n = blockIdx.y, t0 = blockIdx.x * ABT;
    const int b = n >> 4, h = n & 15;
    const int wr0 = wid * 16;
    const int g = lane >> 2, qr = lane & 3;
    const int*   kpmg = kpm + b * T_LEN;
    const size_t nbase = (size_t)n << 16;
    const float* biasg = attn_bias + (size_t)n * T_LEN * T_LEN;

    auto load_kv_stage = [&](int blk) {
        const int s0 = blk * ABS;
        const uint32_t B = sb + AST0 + (uint32_t)(blk & 1) * AST_STRIDE;
#pragma unroll
        for (int it = 0; it < 2; it++) {
            int idx = it * 256 + tid;
            int row = idx >> 3, c = idx & 7;
            uint32_t so = sw128(row * 128 + c * 16);
            size_t go = nbase + (size_t)(s0 + row) * 64 + c * 8;
            cp_async16(B + S_KH + so, g_kh + go);
            cp_async16(B + S_KL + so, g_kl + go);
            cp_async16(B + S_VH + so, g_vh + go);
            cp_async16(B + S_VL + so, g_vl + go);
        }
#pragma unroll
        for (int it = 0; it < 8; it++) {
            int idx = it * 256 + tid;
            int row = idx >> 4, c = idx & 15;
            cp_async16(B + S_BIAS + row * (BIAS_ST * 4) + c * 16,
                       biasg + (size_t)(t0 + row) * T_LEN + s0 + c * 4);
        }
        if (tid < 16) cp_async16(B + S_KPM + tid * 16, kpmg + s0 + tid * 4);
    };

    // --- prologue: Q + stage 0 ---
    {
        const __nv_bfloat16* Qh = g_qh + nbase + (size_t)t0 * 64;
        const __nv_bfloat16* Ql = g_ql + nbase + (size_t)t0 * 64;
#pragma unroll
        for (int it = 0; it < 4; it++) {
            int idx = it * 256 + tid;
            int row = idx >> 3, c = idx & 7;
            uint32_t so = sw128(row * 128 + c * 16);
            cp_async16(sb + AQ_H + so, Qh + row * 64 + c * 8);
            cp_async16(sb + AQ_L + so, Ql + row * 64 + c * 8);
        }
        load_kv_stage(0);
        cp_commit();
    }

    float m0 = -1e30f, m1 = -1e30f, l0 = 0.f, l1 = 0.f;
    float O[8][4];
#pragma unroll
    for (int i = 0; i < 8; i++)
#pragma unroll
        for (int q = 0; q < 4; q++) O[i][q] = 0.f;
    uint32_t qfh[4][4], qfl[4][4];

    const int tr0 = t0 + wr0 + g, tr1 = tr0 + 8;
    const int tl0 = wr0 + g;

    // x4 K addressing (verified R7)
    const int k_mat = lane >> 3;
    const int k_nf_off = k_mat >> 1;
    const int k_k8 = (k_mat & 1) * 8;
    const int k_row = lane & 7;
    // x4 V addressing (trans, verified R7)
    const int v_blk = lane >> 4;
    const int v_row = lane & 15;

    for (int blk = 0; blk < NBLK; blk++) {
        // mask prefetch to regs (independent of smem stages)
        float2 mk0[8], mk1[8];
        {
            const int s0g = blk * ABS;
#pragma unroll
            for (int nf = 0; nf < 8; nf++) {
                const int scol = s0g + nf * 8 + qr * 2;
                mk0[nf] = __ldg(reinterpret_cast<const float2*>(attn_mask + (size_t)tr0 * T_LEN + scol));
                mk1[nf] = __ldg(reinterpret_cast<const float2*>(attn_mask + (size_t)tr1 * T_LEN + scol));
            }
        }
        if (blk + 1 < NBLK) {
            load_kv_stage(blk + 1);
            cp_commit();
            cp_wait<1>();
        } else {
            cp_wait<0>();
        }
        __syncthreads();

        if (blk == 0) {
#pragma unroll
            for (int ks = 0; ks < 4; ks++) {
                uint32_t aoff = sw128((uint32_t)(wr0 + (lane & 15)) * 128 +
                                      (uint32_t)(ks * 16 + (lane >> 4) * 8) * 2);
                ldm_x4(qfh[ks], sb + AQ_H + aoff);
                ldm_x4(qfl[ks], sb + AQ_L + aoff);
            }
        }

        const uint32_t B = sb + AST0 + (uint32_t)(blk & 1) * AST_STRIDE;

        // ---- S = Q K^T (x4 K loads) ----
        float S[8][4];
#pragma unroll
        for (int i = 0; i < 8; i++)
#pragma unroll
            for (int q = 0; q < 4; q++) S[i][q] = 0.f;
#pragma unroll
        for (int ks = 0; ks < 4; ks++) {
#pragma unroll
            for (int nfp = 0; nfp < 4; nfp++) {
                uint32_t boff = sw128((uint32_t)((2 * nfp + k_nf_off) * 8 + k_row) * 128 +
                                      (uint32_t)(ks * 16 + k_k8) * 2);
                uint32_t kh[4], kl[4];
                ldm_x4(kh, B + S_KH + boff);
                ldm_x4(kl, B + S_KL + boff);
#pragma unroll
                for (int half = 0; half < 2; half++) {
                    const int nf = 2 * nfp + half;
                    mma16816(S[nf], qfh[ks], kh + half * 2);
                    mma16816(S[nf], qfh[ks], kl + half * 2);
                    mma16816(S[nf], qfl[ks], kh + half * 2);
                }
            }
        }

        // ---- mask(reg) + bias(smem) + kpm(smem), row max ----
        const int*   kpms   = (const int*)(smc + AST0 + (size_t)(blk & 1) * AST_STRIDE + S_KPM);
        const float* bias_s = (const float*)(smc + AST0 + (size_t)(blk & 1) * AST_STRIDE + S_BIAS);
        float rmax0 = -1e30f, rmax1 = -1e30f;
#pragma unroll
        for (int nf = 0; nf < 8; nf++) {
            const int sloc = nf * 8 + qr * 2;
            const int k0 = kpms[sloc], k1 = kpms[sloc + 1];
            float2 ba = *reinterpret_cast<const float2*>(bias_s + (size_t)tl0 * BIAS_ST + sloc);
            float2 bb = *reinterpret_cast<const float2*>(bias_s + (size_t)(tl0 + 8) * BIAS_ST + sloc);
            S[nf][0] = k0 ? -1e30f : S[nf][0] + mk0[nf].x + ba.x;
            S[nf][1] = k1 ? -1e30f : S[nf][1] + mk0[nf].y + ba.y;
            S[nf][2] = k0 ? -1e30f : S[nf][2] + mk1[nf].x + bb.x;
            S[nf][3] = k1 ? -1e30f : S[nf][3] + mk1[nf].y + bb.y;
            rmax0 = fmaxf(rmax0, fmaxf(S[nf][0], S[nf][1]));
            rmax1 = fmaxf(rmax1, fmaxf(S[nf][2], S[nf][3]));
        }
        rmax0 = fmaxf(rmax0, __shfl_xor_sync(0xffffffffu, rmax0, 1));
        rmax0 = fmaxf(rmax0, __shfl_xor_sync(0xffffffffu, rmax0, 2));
        rmax1 = fmaxf(rmax1, __shfl_xor_sync(0xffffffffu, rmax1, 1));
        rmax1 = fmaxf(rmax1, __shfl_xor_sync(0xffffffffu, rmax1, 2));

        const float mn0 = fmaxf(m0, rmax0), mn1 = fmaxf(m1, rmax1);
        const float es0 = __expf(m0 - mn0), es1 = __expf(m1 - mn1);
        m0 = mn0; m1 = mn1;

        float rs0 = 0.f, rs1 = 0.f;
#pragma unroll
        for (int nf = 0; nf < 8; nf++) {
            S[nf][0] = __expf(S[nf][0] - mn0);
            S[nf][1] = __expf(S[nf][1] - mn0);
            S[nf][2] = __expf(S[nf][2] - mn1);
            S[nf][3] = __expf(S[nf][3] - mn1);
            rs0 += S[nf][0] + S[nf][1];
            rs1 += S[nf][2] + S[nf][3];
        }
        rs0 += __shfl_xor_sync(0xffffffffu, rs0, 1);
        rs0 += __shfl_xor_sync(0xffffffffu, rs0, 2);
        rs1 += __shfl_xor_sync(0xffffffffu, rs1, 1);
        rs1 += __shfl_xor_sync(0xffffffffu, rs1, 2);
        l0 = l0 * es0 + rs0;
        l1 = l1 * es1 + rs1;

#pragma unroll
        for (int i = 0; i < 8; i++) {
            O[i][0] *= es0; O[i][1] *= es0;
            O[i][2] *= es1; O[i][3] *= es1;
        }

        // ---- O += P V (x4 trans V loads) ----
#pragma unroll
        for (int kp = 0; kp < 4; kp++) {
            uint32_t ah[4], al[4];
            ah[0] = pack_hi2(S[2*kp][0],   S[2*kp][1]);
            ah[1] = pack_hi2(S[2*kp][2],   S[2*kp][3]);
            ah[2] = pack_hi2(S[2*kp+1][0], S[2*kp+1][1]);
            ah[3] = pack_hi2(S[2*kp+1][2], S[2*kp+1][3]);
            al[0] = pack_lo2(S[2*kp][0],   S[2*kp][1]);
            al[1] = pack_lo2(S[2*kp][2],   S[2*kp][3]);
            al[2] = pack_lo2(S[2*kp+1][0], S[2*kp+1][1]);
            al[3] = pack_lo2(S[2*kp+1][2], S[2*kp+1][3]);
#pragma unroll
            for (int np = 0; np < 4; np++) {
                uint32_t voff = sw128((uint32_t)(kp * 16 + v_row) * 128 +
                                      (uint32_t)(2 * np + v_blk) * 16);
                uint32_t vh[4], vl[4];
                ldm_x4_trans(vh, B + S_VH + voff);
                ldm_x4_trans(vl, B + S_VL + voff);
#pragma unroll
                for (int half = 0; half < 2; half++) {
                    const int nf2 = 2 * np + half;
                    mma16816(O[nf2], ah, vh + half * 2);
                    mma16816(O[nf2], ah, vl + half * 2);
                    mma16816(O[nf2], al, vh + half * 2);
                }
            }
        }
        __syncthreads();
    }

    // ---- normalize + write bf16 hi/lo ----
    const float inv0 = 1.f / l0, inv1 = 1.f / l1;
    const size_t base0 = ((size_t)tr0 * BSZ + b) * EMBED + h * 64;
    const size_t base1 = ((size_t)tr1 * BSZ + b) * EMBED + h * 64;
#pragma unroll
    for (int nf2 = 0; nf2 < 8; nf2++) {
        const int d0 = nf2 * 8 + qr * 2;
        float v0 = O[nf2][0] * inv0, v1 = O[nf2][1] * inv0;
        float w0 = O[nf2][2] * inv1, w1 = O[nf2][3] * inv1;
        *reinterpret_cast<uint32_t*>(g_attnh + base0 + d0) = pack_hi2(v0, v1);
        *reinterpret_cast<uint32_t*>(g_attnl + base0 + d0) = pack_lo2(v0, v1);
        *reinterpret_cast<uint32_t*>(g_attnh + base1 + d0) = pack_hi2(w0, w1);
        *reinterpret_cast<uint32_t*>(g_attnl + base1 + d0) = pack_lo2(w0, w1);
    }
}

// ---------------------------------------------------------------------------
extern "C" void kernel_launch(void* const* d_in, const int* in_sizes, int n_in,
                              void* d_out, int out_size)
{
    const float* query     = (const float*)d_in[0];
    const int*   kpm       = (const int*)  d_in[1];
    const float* attn_mask = (const float*)d_in[2];
    const float* attn_bias = (const float*)d_in[3];
    const float* W_in      = (const float*)d_in[4];
    const float* b_in      = (const float*)d_in[5];
    const float* W_out     = (const float*)d_in[6];
    const float* b_out     = (const float*)d_in[7];
    float*       out       = (float*)d_out;

    static bool attr_set = false;
    if (!attr_set) {
        cudaFuncSetAttribute(gemm_mma, cudaFuncAttributeMaxDynamicSharedMemorySize, GEMM_SMEM);
        cudaFuncSetAttribute(attn_mma_kernel, cudaFuncAttributeMaxDynamicSharedMemorySize, ATTN_SMEM);
        attr_set = true;
    }

    __nv_bfloat16 *Ah, *Al, *Bh, *Bl, *ATh, *ATl;
    cudaGetSymbolAddress((void**)&Ah, g_Ah);
    cudaGetSymbolAddress((void**)&Al, g_Al);
    cudaGetSymbolAddress((void**)&Bh, g_Bh);
    cudaGetSymbolAddress((void**)&Bl, g_Bl);
    cudaGetSymbolAddress((void**)&ATh, g_attnh);
    cudaGetSymbolAddress((void**)&ATl, g_attnl);

    // 1) split query and W_in to bf16 pairs
    split_kernel<<<MROWS * EMBED / 4 / 256, 256>>>(query, Ah, Al, MROWS * EMBED / 4);
    split_kernel<<<3 * EMBED * EMBED / 4 / 256, 256>>>(W_in, Bh, Bl, 3 * EMBED * EMBED / 4);

    // 2) QKV projection -> bf16 hi/lo q,k,v
    {
        dim3 grid(3 * EMBED / TN, MROWS / TM);
        gemm_mma<<<grid, 256, GEMM_SMEM>>>(Ah, Al, Bh, Bl, b_in, 0, nullptr);
    }

    // 3) Flash attention
    {
        dim3 grid(T_LEN / ABT, NBH);   // (8, 64)
        attn_mma_kernel<<<grid, 256, ATTN_SMEM>>>(kpm, attn_mask, attn_bias);
    }

    // 4) split W_out; output projection (A = attn bf16 pairs)
    split_kernel<<<EMBED * EMBED / 4 / 256, 256>>>(W_out, Bh, Bl, EMBED * EMBED / 4);
    {
        dim3 grid(EMBED / TN, MROWS / TM);
        gemm_mma<<<grid, 256, GEMM_SMEM>>>(ATh, ATl, Bh, Bl, b_out, 1, out);
    }
}

// round 9
// speedup vs baseline: 1.3822x; 1.3822x over previous
#include <cuda_runtime.h>
#include <cuda_bf16.h>
#include <cstdint>

// Problem constants
#define T_LEN   1024
#define BSZ     4
#define EMBED   1024
#define NHEADS  16
#define HDIM    64
#define NBH     (BSZ * NHEADS)      // 64
#define MROWS   (T_LEN * BSZ)       // 4096
#define SCALING 0.125f

// bf16 hi/lo scratch (q scaled)
__device__ __nv_bfloat16 g_qh[NBH * T_LEN * HDIM];
__device__ __nv_bfloat16 g_ql[NBH * T_LEN * HDIM];
__device__ __nv_bfloat16 g_kh[NBH * T_LEN * HDIM];
__device__ __nv_bfloat16 g_kl[NBH * T_LEN * HDIM];
__device__ __nv_bfloat16 g_vh[NBH * T_LEN * HDIM];
__device__ __nv_bfloat16 g_vl[NBH * T_LEN * HDIM];
__device__ __nv_bfloat16 g_attnh[MROWS * EMBED];
__device__ __nv_bfloat16 g_attnl[MROWS * EMBED];
// bf16 split GEMM operands
__device__ __nv_bfloat16 g_Ah[MROWS * EMBED];
__device__ __nv_bfloat16 g_Al[MROWS * EMBED];
__device__ __nv_bfloat16 g_Bh[3 * EMBED * EMBED];
__device__ __nv_bfloat16 g_Bl[3 * EMBED * EMBED];

// ---------------------------------------------------------------------------
// PTX helpers
// ---------------------------------------------------------------------------
__device__ __forceinline__ uint32_t s2u(const void* p) {
    return (uint32_t)__cvta_generic_to_shared(p);
}
__device__ __forceinline__ void cp_async16(uint32_t dst, const void* src) {
    asm volatile("cp.async.cg.shared.global [%0], [%1], 16;\n" :: "r"(dst), "l"(src));
}
__device__ __forceinline__ void cp_commit() {
    asm volatile("cp.async.commit_group;\n");
}
template<int N>
__device__ __forceinline__ void cp_wait() {
    asm volatile("cp.async.wait_group %0;\n" :: "n"(N));
}
__device__ __forceinline__ void ldm_x4(uint32_t* r, uint32_t addr) {
    asm volatile("ldmatrix.sync.aligned.m8n8.x4.shared.b16 {%0,%1,%2,%3}, [%4];"
                 : "=r"(r[0]), "=r"(r[1]), "=r"(r[2]), "=r"(r[3]) : "r"(addr));
}
__device__ __forceinline__ void ldm_x2(uint32_t* r, uint32_t addr) {
    asm volatile("ldmatrix.sync.aligned.m8n8.x2.shared.b16 {%0,%1}, [%2];"
                 : "=r"(r[0]), "=r"(r[1]) : "r"(addr));
}
__device__ __forceinline__ void ldm_x2_trans(uint32_t* r, uint32_t addr) {
    asm volatile("ldmatrix.sync.aligned.m8n8.x2.trans.shared.b16 {%0,%1}, [%2];"
                 : "=r"(r[0]), "=r"(r[1]) : "r"(addr));
}
__device__ __forceinline__ void mma16816(float* c, const uint32_t* a, const uint32_t* b) {
    asm volatile("mma.sync.aligned.m16n8k16.row.col.f32.bf16.bf16.f32 "
                 "{%0,%1,%2,%3}, {%4,%5,%6,%7}, {%8,%9}, {%0,%1,%2,%3};"
                 : "+f"(c[0]), "+f"(c[1]), "+f"(c[2]), "+f"(c[3])
                 : "r"(a[0]), "r"(a[1]), "r"(a[2]), "r"(a[3]), "r"(b[0]), "r"(b[1]));
}
__device__ __host__ __forceinline__ uint32_t sw128(uint32_t off) {
    return off ^ ((off >> 3) & 0x70);
}
__device__ __forceinline__ uint32_t pack_hi2(float a, float b) {
    __nv_bfloat162 t; t.x = __float2bfloat16(a); t.y = __float2bfloat16(b);
    uint32_t r; memcpy(&r, &t, 4); return r;
}
__device__ __forceinline__ uint32_t pack_lo2(float a, float b) {
    __nv_bfloat16 ha = __float2bfloat16(a), hb = __float2bfloat16(b);
    __nv_bfloat162 t;
    t.x = __float2bfloat16(a - __bfloat162float(ha));
    t.y = __float2bfloat16(b - __bfloat162float(hb));
    uint32_t r; memcpy(&r, &t, 4); return r;
}

// ---------------------------------------------------------------------------
// fp32 -> (hi, lo) bf16 split
// ---------------------------------------------------------------------------
__global__ __launch_bounds__(256)
void split_kernel(const float* __restrict__ src, __nv_bfloat16* __restrict__ hi,
                  __nv_bfloat16* __restrict__ lo, int n4)
{
    int i = blockIdx.x * 256 + threadIdx.x;
    if (i >= n4) return;
    float4 v = reinterpret_cast<const float4*>(src)[i];
    reinterpret_cast<uint32_t*>(hi)[2 * i]     = pack_hi2(v.x, v.y);
    reinterpret_cast<uint32_t*>(hi)[2 * i + 1] = pack_hi2(v.z, v.w);
    reinterpret_cast<uint32_t*>(lo)[2 * i]     = pack_lo2(v.x, v.y);
    reinterpret_cast<uint32_t*>(lo)[2 * i + 1] = pack_lo2(v.z, v.w);
}

// ---------------------------------------------------------------------------
// mma.sync split-bf16 GEMM — 512 threads / 16 warps, 32x32 warp tile,
// 2-stage cp.async pipeline (80KB smem). Same math order as before.
// ---------------------------------------------------------------------------
#define GK 1024
#define TM 128
#define TN 128
#define TBK 32
#define NKS (GK / TBK)
#define A_ST 40
#define TILE_B (128 * A_ST * 2)
#define STAGE_B (4 * TILE_B)
#define GEMM_SMEM (2 * STAGE_B)   // 81920

__device__ __forceinline__ void load_stage(uint32_t sbase,
    const __nv_bfloat16* __restrict__ Ah, const __nv_bfloat16* __restrict__ Al,
    const __nv_bfloat16* __restrict__ Bh, const __nv_bfloat16* __restrict__ Bl,
    int row0, int col0, int k0, int tid)
{
    // 512 threads: one 16B chunk per thread per array
    int r = tid >> 2, c = tid & 3;
    uint32_t so = r * (A_ST * 2) + c * 16;
    size_t ga = (size_t)(row0 + r) * GK + k0 + c * 8;
    size_t gb = (size_t)(col0 + r) * GK + k0 + c * 8;
    cp_async16(sbase + 0 * TILE_B + so, Ah + ga);
    cp_async16(sbase + 1 * TILE_B + so, Al + ga);
    cp_async16(sbase + 2 * TILE_B + so, Bh + gb);
    cp_async16(sbase + 3 * TILE_B + so, Bl + gb);
}

__global__ __launch_bounds__(512)
void gemm_mma(const __nv_bfloat16* __restrict__ Ah, const __nv_bfloat16* __restrict__ Al,
              const __nv_bfloat16* __restrict__ Bh, const __nv_bfloat16* __restrict__ Bl,
              const float* __restrict__ bias, int mode, float* __restrict__ out)
{
    extern __shared__ char smc[];
    const uint32_t sb = s2u(smc);
    const int tid  = threadIdx.x;
    const int lane = tid & 31;
    const int wid  = tid >> 5;      // 0..15
    const int wr = wid & 3;         // 4 row groups of 32
    const int wc = wid >> 2;        // 4 col groups of 32
    const int row0 = blockIdx.y * TM, col0 = blockIdx.x * TN;

    const int a_row = lane & 15;
    const int a_k8  = (lane >> 4) * 8;
    const int b_row = lane & 7;
    const int b_k8  = ((lane >> 3) & 1) * 8;

    float acc[2][4][4];
#pragma unroll
    for (int i = 0; i < 2; i++)
#pragma unroll
        for (int j = 0; j < 4; j++)
#pragma unroll
            for (int q = 0; q < 4; q++) acc[i][j][q] = 0.f;

    load_stage(sb, Ah, Al, Bh, Bl, row0, col0, 0, tid);
    cp_commit();

    for (int ks = 0; ks < NKS; ks++) {
        const uint32_t cur = sb + (uint32_t)(ks & 1) * STAGE_B;
        if (ks + 1 < NKS) {
            load_stage(sb + (uint32_t)((ks + 1) & 1) * STAGE_B,
                       Ah, Al, Bh, Bl, row0, col0, (ks + 1) * TBK, tid);
            cp_commit();
            cp_wait<1>();
        } else {
            cp_wait<0>();
        }
        __syncthreads();

#pragma unroll
        for (int kk = 0; kk < 2; kk++) {
            const int k0 = kk * 16;
            uint32_t afh[2][4], afl[2][4];
#pragma unroll
            for (int mf = 0; mf < 2; mf++) {
                uint32_t aoff = (uint32_t)((wr * 32 + mf * 16 + a_row) * A_ST + k0 + a_k8) * 2;
                ldm_x4(afh[mf], cur + 0 * TILE_B + aoff);
                ldm_x4(afl[mf], cur + 1 * TILE_B + aoff);
            }
            uint32_t bfh[4][2], bfl[4][2];
#pragma unroll
            for (int nf = 0; nf < 4; nf++) {
                uint32_t boff = (uint32_t)((wc * 32 + nf * 8 + b_row) * A_ST + k0 + b_k8) * 2;
                ldm_x2(bfh[nf], cur + 2 * TILE_B + boff);
                ldm_x2(bfl[nf], cur + 3 * TILE_B + boff);
            }
#pragma unroll
            for (int mf = 0; mf < 2; mf++)
#pragma unroll
                for (int nf = 0; nf < 4; nf++) {
                    mma16816(acc[mf][nf], afh[mf], bfh[nf]);
                    mma16816(acc[mf][nf], afh[mf], bfl[nf]);
                    mma16816(acc[mf][nf], afl[mf], bfh[nf]);
                }
        }
        __syncthreads();
    }

    const int g = lane >> 2, tig = lane & 3;
#pragma unroll
    for (int nf = 0; nf < 4; nf++) {
        const int e = col0 + wc * 32 + nf * 8 + tig * 2;
        const float bz0 = __ldg(bias + e);
        const float bz1 = __ldg(bias + e + 1);
#pragma unroll
        for (int mf = 0; mf < 2; mf++) {
#pragma unroll
            for (int half = 0; half < 2; half++) {
                const int m = row0 + wr * 32 + mf * 16 + g + half * 8;
                float v0 = acc[mf][nf][half * 2 + 0] + bz0;
                float v1 = acc[mf][nf][half * 2 + 1] + bz1;
                if (mode == 0) {
                    const int t = m >> 2, b = m & 3;
                    const int which = e >> 10;
                    const int rem = e & 1023;
                    const int h = rem >> 6, d = rem & 63;
                    const int n = (b << 4) + h;
                    if (which == 0) { v0 *= SCALING; v1 *= SCALING; }
                    __nv_bfloat16* dh = (which == 0) ? g_qh : (which == 1) ? g_kh : g_vh;
                    __nv_bfloat16* dl = (which == 0) ? g_ql : (which == 1) ? g_kl : g_vl;
                    size_t off = ((size_t)n << 16) + ((size_t)t << 6) + d;
                    *reinterpret_cast<uint32_t*>(dh + off) = pack_hi2(v0, v1);
                    *reinterpret_cast<uint32_t*>(dl + off) = pack_lo2(v0, v1);
                } else {
                    *reinterpret_cast<float2*>(out + (size_t)m * EMBED + e)
                        = make_float2(v0, v1);
                }
            }
        }
    }
}

// ---------------------------------------------------------------------------
// Flash attention — exact R6 kernel (best measured: 235us).
// ---------------------------------------------------------------------------
#define ABT 128
#define ABS 64
#define NBLK (T_LEN / ABS)   // 16
#define AQ_H   0
#define AQ_L   16384
#define AST0   32768
#define S_KH    0
#define S_KL    8192
#define S_VH    16384
#define S_VL    24576
#define S_BIAS  32768
#define BIAS_ST 68
#define S_KPM   (32768 + 128 * BIAS_ST * 4)   // 67584
#define AST_STRIDE (S_KPM + 256)              // 67840
#define ATTN_SMEM (AST0 + 2 * AST_STRIDE)     // 168448

__global__ __launch_bounds__(256, 1)
void attn_mma_kernel(const int*   __restrict__ kpm,
                     const float* __restrict__ attn_mask,
                     const float* __restrict__ attn_bias)
{
    extern __shared__ char smc[];
    const uint32_t sb = s2u(smc);
    const int tid = threadIdx.x, lane = tid & 31, wid = tid >> 5;
    const int n = blockIdx.y, t0 = blockIdx.x * ABT;
    const int b = n >> 4, h = n & 15;
    const int wr0 = wid * 16;
    const int g = lane >> 2, qr = lane & 3;
    const int*   kpmg = kpm + b * T_LEN;
    const size_t nbase = (size_t)n << 16;
    const float* biasg = attn_bias + (size_t)n * T_LEN * T_LEN;

    auto load_kv_stage = [&](int blk) {
        const int s0 = blk * ABS;
        const uint32_t B = sb + AST0 + (uint32_t)(blk & 1) * AST_STRIDE;
#pragma unroll
        for (int it = 0; it < 2; it++) {
            int idx = it * 256 + tid;
            int row = idx >> 3, c = idx & 7;
            uint32_t so = sw128(row * 128 + c * 16);
            size_t go = nbase + (size_t)(s0 + row) * 64 + c * 8;
            cp_async16(B + S_KH + so, g_kh + go);
            cp_async16(B + S_KL + so, g_kl + go);
            cp_async16(B + S_VH + so, g_vh + go);
            cp_async16(B + S_VL + so, g_vl + go);
        }
#pragma unroll
        for (int it = 0; it < 8; it++) {
            int idx = it * 256 + tid;
            int row = idx >> 4, c = idx & 15;
            cp_async16(B + S_BIAS + row * (BIAS_ST * 4) + c * 16,
                       biasg + (size_t)(t0 + row) * T_LEN + s0 + c * 4);
        }
        if (tid < 16) cp_async16(B + S_KPM + tid * 16, kpmg + s0 + tid * 4);
    };

    // --- prologue: Q + stage 0 ---
    {
        const __nv_bfloat16* Qh = g_qh + nbase + (size_t)t0 * 64;
        const __nv_bfloat16* Ql = g_ql + nbase + (size_t)t0 * 64;
#pragma unroll
        for (int it = 0; it < 4; it++) {
            int idx = it * 256 + tid;
            int row = idx >> 3, c = idx & 7;
            uint32_t so = sw128(row * 128 + c * 16);
            cp_async16(sb + AQ_H + so, Qh + row * 64 + c * 8);
            cp_async16(sb + AQ_L + so, Ql + row * 64 + c * 8);
        }
        load_kv_stage(0);
        cp_commit();
    }

    float m0 = -1e30f, m1 = -1e30f, l0 = 0.f, l1 = 0.f;
    float O[8][4];
#pragma unroll
    for (int i = 0; i < 8; i++)
#pragma unroll
        for (int q = 0; q < 4; q++) O[i][q] = 0.f;
    uint32_t qfh[4][4], qfl[4][4];

    const int tr0 = t0 + wr0 + g, tr1 = tr0 + 8;
    const int tl0 = wr0 + g;

    for (int blk = 0; blk < NBLK; blk++) {
        // mask prefetch to regs
        float2 mk0[8], mk1[8];
        {
            const int s0g = blk * ABS;
#pragma unroll
            for (int nf = 0; nf < 8; nf++) {
                const int scol = s0g + nf * 8 + qr * 2;
                mk0[nf] = __ldg(reinterpret_cast<const float2*>(attn_mask + (size_t)tr0 * T_LEN + scol));
                mk1[nf] = __ldg(reinterpret_cast<const float2*>(attn_mask + (size_t)tr1 * T_LEN + scol));
            }
        }
        if (blk + 1 < NBLK) {
            load_kv_stage(blk + 1);
            cp_commit();
            cp_wait<1>();
        } else {
            cp_wait<0>();
        }
        __syncthreads();

        if (blk == 0) {
#pragma unroll
            for (int ks = 0; ks < 4; ks++) {
                uint32_t aoff = sw128((uint32_t)(wr0 + (lane & 15)) * 128 +
                                      (uint32_t)(ks * 16 + (lane >> 4) * 8) * 2);
                ldm_x4(qfh[ks], sb + AQ_H + aoff);
                ldm_x4(qfl[ks], sb + AQ_L + aoff);
            }
        }

        const uint32_t B = sb + AST0 + (uint32_t)(blk & 1) * AST_STRIDE;

        // ---- S = Q K^T ----
        float S[8][4];
#pragma unroll
        for (int i = 0; i < 8; i++)
#pragma unroll
            for (int q = 0; q < 4; q++) S[i][q] = 0.f;
#pragma unroll
        for (int ks = 0; ks < 4; ks++) {
#pragma unroll
            for (int nf = 0; nf < 8; nf++) {
                uint32_t boff = sw128((uint32_t)(nf * 8 + (lane & 7)) * 128 +
                                      (uint32_t)(ks * 16 + ((lane >> 3) & 1) * 8) * 2);
                uint32_t kh[2], kl[2];
                ldm_x2(kh, B + S_KH + boff);
                ldm_x2(kl, B + S_KL + boff);
                mma16816(S[nf], qfh[ks], kh);
                mma16816(S[nf], qfh[ks], kl);
                mma16816(S[nf], qfl[ks], kh);
            }
        }

        // ---- mask(reg) + bias(smem) + kpm(smem), row max ----
        const int*   kpms   = (const int*)(smc + AST0 + (size_t)(blk & 1) * AST_STRIDE + S_KPM);
        const float* bias_s = (const float*)(smc + AST0 + (size_t)(blk & 1) * AST_STRIDE + S_BIAS);
        float rmax0 = -1e30f, rmax1 = -1e30f;
#pragma unroll
        for (int nf = 0; nf < 8; nf++) {
            const int sloc = nf * 8 + qr * 2;
            const int k0 = kpms[sloc], k1 = kpms[sloc + 1];
            float2 ba = *reinterpret_cast<const float2*>(bias_s + (size_t)tl0 * BIAS_ST + sloc);
            float2 bb = *reinterpret_cast<const float2*>(bias_s + (size_t)(tl0 + 8) * BIAS_ST + sloc);
            S[nf][0] = k0 ? -1e30f : S[nf][0] + mk0[nf].x + ba.x;
            S[nf][1] = k1 ? -1e30f : S[nf][1] + mk0[nf].y + ba.y;
            S[nf][2] = k0 ? -1e30f : S[nf][2] + mk1[nf].x + bb.x;
            S[nf][3] = k1 ? -1e30f : S[nf][3] + mk1[nf].y + bb.y;
            rmax0 = fmaxf(rmax0, fmaxf(S[nf][0], S[nf][1]));
            rmax1 = fmaxf(rmax1, fmaxf(S[nf][2], S[nf][3]));
        }
        rmax0 = fmaxf(rmax0, __shfl_xor_sync(0xffffffffu, rmax0, 1));
        rmax0 = fmaxf(rmax0, __shfl_xor_sync(0xffffffffu, rmax0, 2));
        rmax1 = fmaxf(rmax1, __shfl_xor_sync(0xffffffffu, rmax1, 1));
        rmax1 = fmaxf(rmax1, __shfl_xor_sync(0xffffffffu, rmax1, 2));

        const float mn0 = fmaxf(m0, rmax0), mn1 = fmaxf(m1, rmax1);
        const float es0 = __expf(m0 - mn0), es1 = __expf(m1 - mn1);
        m0 = mn0; m1 = mn1;

        float rs0 = 0.f, rs1 = 0.f;
#pragma unroll
        for (int nf = 0; nf < 8; nf++) {
            S[nf][0] = __expf(S[nf][0] - mn0);
            S[nf][1] = __expf(S[nf][1] - mn0);
            S[nf][2] = __expf(S[nf][2] - mn1);
            S[nf][3] = __expf(S[nf][3] - mn1);
            rs0 += S[nf][0] + S[nf][1];
            rs1 += S[nf][2] + S[nf][3];
        }
        rs0 += __shfl_xor_sync(0xffffffffu, rs0, 1);
        rs0 += __shfl_xor_sync(0xffffffffu, rs0, 2);
        rs1 += __shfl_xor_sync(0xffffffffu, rs1, 1);
        rs1 += __shfl_xor_sync(0xffffffffu, rs1, 2);
        l0 = l0 * es0 + rs0;
        l1 = l1 * es1 + rs1;

#pragma unroll
        for (int i = 0; i < 8; i++) {
            O[i][0] *= es0; O[i][1] *= es0;
            O[i][2] *= es1; O[i][3] *= es1;
        }

        // ---- O += P V ----
#pragma unroll
        for (int kp = 0; kp < 4; kp++) {
            uint32_t ah[4], al[4];
            ah[0] = pack_hi2(S[2*kp][0],   S[2*kp][1]);
            ah[1] = pack_hi2(S[2*kp][2],   S[2*kp][3]);
            ah[2] = pack_hi2(S[2*kp+1][0], S[2*kp+1][1]);
            ah[3] = pack_hi2(S[2*kp+1][2], S[2*kp+1][3]);
            al[0] = pack_lo2(S[2*kp][0],   S[2*kp][1]);
            al[1] = pack_lo2(S[2*kp][2],   S[2*kp][3]);
            al[2] = pack_lo2(S[2*kp+1][0], S[2*kp+1][1]);
            al[3] = pack_lo2(S[2*kp+1][2], S[2*kp+1][3]);
#pragma unroll
            for (int nf2 = 0; nf2 < 8; nf2++) {
                uint32_t voff = sw128((uint32_t)(kp * 16 + (lane & 15)) * 128 +
                                      (uint32_t)nf2 * 16);
                uint32_t vh[2], vl[2];
                ldm_x2_trans(vh, B + S_VH + voff);
                ldm_x2_trans(vl, B + S_VL + voff);
                mma16816(O[nf2], ah, vh);
                mma16816(O[nf2], ah, vl);
                mma16816(O[nf2], al, vh);
            }
        }
        __syncthreads();
    }

    // ---- normalize + write bf16 hi/lo ----
    const float inv0 = 1.f / l0, inv1 = 1.f / l1;
    const size_t base0 = ((size_t)tr0 * BSZ + b) * EMBED + h * 64;
    const size_t base1 = ((size_t)tr1 * BSZ + b) * EMBED + h * 64;
#pragma unroll
    for (int nf2 = 0; nf2 < 8; nf2++) {
        const int d0 = nf2 * 8 + qr * 2;
        float v0 = O[nf2][0] * inv0, v1 = O[nf2][1] * inv0;
        float w0 = O[nf2][2] * inv1, w1 = O[nf2][3] * inv1;
        *reinterpret_cast<uint32_t*>(g_attnh + base0 + d0) = pack_hi2(v0, v1);
        *reinterpret_cast<uint32_t*>(g_attnl + base0 + d0) = pack_lo2(v0, v1);
        *reinterpret_cast<uint32_t*>(g_attnh + base1 + d0) = pack_hi2(w0, w1);
        *reinterpret_cast<uint32_t*>(g_attnl + base1 + d0) = pack_lo2(w0, w1);
    }
}

// ---------------------------------------------------------------------------
extern "C" void kernel_launch(void* const* d_in, const int* in_sizes, int n_in,
                              void* d_out, int out_size)
{
    const float* query     = (const float*)d_in[0];
    const int*   kpm       = (const int*)  d_in[1];
    const float* attn_mask = (const float*)d_in[2];
    const float* attn_bias = (const float*)d_in[3];
    const float* W_in      = (const float*)d_in[4];
    const float* b_in      = (const float*)d_in[5];
    const float* W_out     = (const float*)d_in[6];
    const float* b_out     = (const float*)d_in[7];
    float*       out       = (float*)d_out;

    static bool attr_set = false;
    if (!attr_set) {
        cudaFuncSetAttribute(gemm_mma, cudaFuncAttributeMaxDynamicSharedMemorySize, GEMM_SMEM);
        cudaFuncSetAttribute(attn_mma_kernel, cudaFuncAttributeMaxDynamicSharedMemorySize, ATTN_SMEM);
        attr_set = true;
    }

    __nv_bfloat16 *Ah, *Al, *Bh, *Bl, *ATh, *ATl;
    cudaGetSymbolAddress((void**)&Ah, g_Ah);
    cudaGetSymbolAddress((void**)&Al, g_Al);
    cudaGetSymbolAddress((void**)&Bh, g_Bh);
    cudaGetSymbolAddress((void**)&Bl, g_Bl);
    cudaGetSymbolAddress((void**)&ATh, g_attnh);
    cudaGetSymbolAddress((void**)&ATl, g_attnl);

    // 1) split query and W_in to bf16 pairs
    split_kernel<<<MROWS * EMBED / 4 / 256, 256>>>(query, Ah, Al, MROWS * EMBED / 4);
    split_kernel<<<3 * EMBED * EMBED / 4 / 256, 256>>>(W_in, Bh, Bl, 3 * EMBED * EMBED / 4);

    // 2) QKV projection -> bf16 hi/lo q,k,v (512-thread CTAs, 16 warps)
    {
        dim3 grid(3 * EMBED / TN, MROWS / TM);   // (24, 32)
        gemm_mma<<<grid, 512, GEMM_SMEM>>>(Ah, Al, Bh, Bl, b_in, 0, nullptr);
    }

    // 3) Flash attention (R6 kernel)
    {
        dim3 grid(T_LEN / ABT, NBH);   // (8, 64)
        attn_mma_kernel<<<grid, 256, ATTN_SMEM>>>(kpm, attn_mask, attn_bias);
    }

    // 4) split W_out; output projection
    split_kernel<<<EMBED * EMBED / 4 / 256, 256>>>(W_out, Bh, Bl, EMBED * EMBED / 4);
    {
        dim3 grid(EMBED / TN, MROWS / TM);       // (8, 32)
        gemm_mma<<<grid, 512, GEMM_SMEM>>>(ATh, ATl, Bh, Bl, b_out, 1, out);
    }
}

// round 10
// speedup vs baseline: 1.9764x; 1.4299x over previous
#include <cuda_runtime.h>
#include <cuda_fp16.h>
#include <cstdint>

// Problem constants
#define T_LEN   1024
#define BSZ     4
#define EMBED   1024
#define NHEADS  16
#define HDIM    64
#define NBH     (BSZ * NHEADS)      // 64
#define MROWS   (T_LEN * BSZ)       // 4096
#define SCALING 0.125f

// fp16 hi/lo scratch (q scaled, hi only; k/v hi+lo)
__device__ __half g_qh[NBH * T_LEN * HDIM];
__device__ __half g_kh[NBH * T_LEN * HDIM];
__device__ __half g_kl[NBH * T_LEN * HDIM];
__device__ __half g_vh[NBH * T_LEN * HDIM];
__device__ __half g_vl[NBH * T_LEN * HDIM];
__device__ __half g_attnh[MROWS * EMBED];
// fp16 split GEMM operands
__device__ __half g_Ah[MROWS * EMBED];
__device__ __half g_Al[MROWS * EMBED];      // written by split, unused by gemm (A-lo dropped)
__device__ __half g_Bh[3 * EMBED * EMBED];
__device__ __half g_Bl[3 * EMBED * EMBED];

// ---------------------------------------------------------------------------
// PTX helpers
// ---------------------------------------------------------------------------
__device__ __forceinline__ uint32_t s2u(const void* p) {
    return (uint32_t)__cvta_generic_to_shared(p);
}
__device__ __forceinline__ void cp_async16(uint32_t dst, const void* src) {
    asm volatile("cp.async.cg.shared.global [%0], [%1], 16;\n" :: "r"(dst), "l"(src));
}
__device__ __forceinline__ void cp_commit() {
    asm volatile("cp.async.commit_group;\n");
}
template<int N>
__device__ __forceinline__ void cp_wait() {
    asm volatile("cp.async.wait_group %0;\n" :: "n"(N));
}
__device__ __forceinline__ void ldm_x4(uint32_t* r, uint32_t addr) {
    asm volatile("ldmatrix.sync.aligned.m8n8.x4.shared.b16 {%0,%1,%2,%3}, [%4];"
                 : "=r"(r[0]), "=r"(r[1]), "=r"(r[2]), "=r"(r[3]) : "r"(addr));
}
__device__ __forceinline__ void ldm_x2(uint32_t* r, uint32_t addr) {
    asm volatile("ldmatrix.sync.aligned.m8n8.x2.shared.b16 {%0,%1}, [%2];"
                 : "=r"(r[0]), "=r"(r[1]) : "r"(addr));
}
__device__ __forceinline__ void ldm_x2_trans(uint32_t* r, uint32_t addr) {
    asm volatile("ldmatrix.sync.aligned.m8n8.x2.trans.shared.b16 {%0,%1}, [%2];"
                 : "=r"(r[0]), "=r"(r[1]) : "r"(addr));
}
// fp16 MMA, fp32 accumulate
__device__ __forceinline__ void mma16816(float* c, const uint32_t* a, const uint32_t* b) {
    asm volatile("mma.sync.aligned.m16n8k16.row.col.f32.f16.f16.f32 "
                 "{%0,%1,%2,%3}, {%4,%5,%6,%7}, {%8,%9}, {%0,%1,%2,%3};"
                 : "+f"(c[0]), "+f"(c[1]), "+f"(c[2]), "+f"(c[3])
                 : "r"(a[0]), "r"(a[1]), "r"(a[2]), "r"(a[3]), "r"(b[0]), "r"(b[1]));
}
__device__ __host__ __forceinline__ uint32_t sw128(uint32_t off) {
    return off ^ ((off >> 3) & 0x70);
}
__device__ __forceinline__ uint32_t pack_hi2(float a, float b) {
    __half2 t; t.x = __float2half_rn(a); t.y = __float2half_rn(b);
    uint32_t r; memcpy(&r, &t, 4); return r;
}
__device__ __forceinline__ uint32_t pack_lo2(float a, float b) {
    __half ha = __float2half_rn(a), hb = __float2half_rn(b);
    __half2 t;
    t.x = __float2half_rn(a - __half2float(ha));
    t.y = __float2half_rn(b - __half2float(hb));
    uint32_t r; memcpy(&r, &t, 4); return r;
}

// ---------------------------------------------------------------------------
// fp32 -> (hi, lo) fp16 split
// ---------------------------------------------------------------------------
__global__ __launch_bounds__(256)
void split_kernel(const float* __restrict__ src, __half* __restrict__ hi,
                  __half* __restrict__ lo, int n4)
{
    int i = blockIdx.x * 256 + threadIdx.x;
    if (i >= n4) return;
    float4 v = reinterpret_cast<const float4*>(src)[i];
    reinterpret_cast<uint32_t*>(hi)[2 * i]     = pack_hi2(v.x, v.y);
    reinterpret_cast<uint32_t*>(hi)[2 * i + 1] = pack_hi2(v.z, v.w);
    reinterpret_cast<uint32_t*>(lo)[2 * i]     = pack_lo2(v.x, v.y);
    reinterpret_cast<uint32_t*>(lo)[2 * i + 1] = pack_lo2(v.z, v.w);
}

// ---------------------------------------------------------------------------
// mma.sync fp16 2-product GEMM: D = Ah*(Bh+Bl). R6 structure, Al tile removed.
// 256 threads, 8 warps x (64x32), 2-stage cp.async (60KB smem).
// ---------------------------------------------------------------------------
#define GK 1024
#define TM 128
#define TN 128
#define TBK 32
#define NKS (GK / TBK)
#define A_ST 40
#define TILE_B (128 * A_ST * 2)     // 10240
#define STAGE_B (3 * TILE_B)        // Ah, Bh, Bl
#define GEMM_SMEM (2 * STAGE_B)     // 61440

__device__ __forceinline__ void load_stage(uint32_t sbase,
    const __half* __restrict__ Ah,
    const __half* __restrict__ Bh, const __half* __restrict__ Bl,
    int row0, int col0, int k0, int tid)
{
#pragma unroll
    for (int it = 0; it < 2; it++) {
        int idx = it * 256 + tid;
        int r = idx >> 2, c = idx & 3;
        uint32_t so = r * (A_ST * 2) + c * 16;
        size_t ga = (size_t)(row0 + r) * GK + k0 + c * 8;
        size_t gb = (size_t)(col0 + r) * GK + k0 + c * 8;
        cp_async16(sbase + 0 * TILE_B + so, Ah + ga);
        cp_async16(sbase + 1 * TILE_B + so, Bh + gb);
        cp_async16(sbase + 2 * TILE_B + so, Bl + gb);
    }
}

__global__ __launch_bounds__(256)
void gemm_mma(const __half* __restrict__ Ah,
              const __half* __restrict__ Bh, const __half* __restrict__ Bl,
              const float* __restrict__ bias, int mode, float* __restrict__ out)
{
    extern __shared__ char smc[];
    const uint32_t sb = s2u(smc);
    const int tid  = threadIdx.x;
    const int lane = tid & 31;
    const int wid  = tid >> 5;
    const int wr = wid & 1;
    const int wc = wid >> 1;
    const int row0 = blockIdx.y * TM, col0 = blockIdx.x * TN;

    const int a_row = lane & 15;
    const int a_k8  = (lane >> 4) * 8;
    const int b_row = lane & 7;
    const int b_k8  = ((lane >> 3) & 1) * 8;

    float acc[4][4][4];
#pragma unroll
    for (int i = 0; i < 4; i++)
#pragma unroll
        for (int j = 0; j < 4; j++)
#pragma unroll
            for (int q = 0; q < 4; q++) acc[i][j][q] = 0.f;

    load_stage(sb, Ah, Bh, Bl, row0, col0, 0, tid);
    cp_commit();

    for (int ks = 0; ks < NKS; ks++) {
        const uint32_t cur = sb + (uint32_t)(ks & 1) * STAGE_B;
        if (ks + 1 < NKS) {
            load_stage(sb + (uint32_t)((ks + 1) & 1) * STAGE_B,
                       Ah, Bh, Bl, row0, col0, (ks + 1) * TBK, tid);
            cp_commit();
            cp_wait<1>();
        } else {
            cp_wait<0>();
        }
        __syncthreads();

#pragma unroll
        for (int kk = 0; kk < 2; kk++) {
            const int k0 = kk * 16;
            uint32_t afh[4][4];
#pragma unroll
            for (int mf = 0; mf < 4; mf++) {
                uint32_t aoff = (uint32_t)((wr * 64 + mf * 16 + a_row) * A_ST + k0 + a_k8) * 2;
                ldm_x4(afh[mf], cur + 0 * TILE_B + aoff);
            }
            uint32_t bfh[4][2], bfl[4][2];
#pragma unroll
            for (int nf = 0; nf < 4; nf++) {
                uint32_t boff = (uint32_t)((wc * 32 + nf * 8 + b_row) * A_ST + k0 + b_k8) * 2;
                ldm_x2(bfh[nf], cur + 1 * TILE_B + boff);
                ldm_x2(bfl[nf], cur + 2 * TILE_B + boff);
            }
#pragma unroll
            for (int mf = 0; mf < 4; mf++)
#pragma unroll
                for (int nf = 0; nf < 4; nf++) {
                    mma16816(acc[mf][nf], afh[mf], bfh[nf]);
                    mma16816(acc[mf][nf], afh[mf], bfl[nf]);
                }
        }
        __syncthreads();
    }

    const int g = lane >> 2, tig = lane & 3;
#pragma unroll
    for (int nf = 0; nf < 4; nf++) {
        const int e = col0 + wc * 32 + nf * 8 + tig * 2;
        const float bz0 = __ldg(bias + e);
        const float bz1 = __ldg(bias + e + 1);
#pragma unroll
        for (int mf = 0; mf < 4; mf++) {
#pragma unroll
            for (int half = 0; half < 2; half++) {
                const int m = row0 + wr * 64 + mf * 16 + g + half * 8;
                float v0 = acc[mf][nf][half * 2 + 0] + bz0;
                float v1 = acc[mf][nf][half * 2 + 1] + bz1;
                if (mode == 0) {
                    const int t = m >> 2, b = m & 3;
                    const int which = e >> 10;
                    const int rem = e & 1023;
                    const int h = rem >> 6, d = rem & 63;
                    const int n = (b << 4) + h;
                    size_t off = ((size_t)n << 16) + ((size_t)t << 6) + d;
                    if (which == 0) {
                        v0 *= SCALING; v1 *= SCALING;
                        *reinterpret_cast<uint32_t*>(g_qh + off) = pack_hi2(v0, v1);
                    } else {
                        __half* dh = (which == 1) ? g_kh : g_vh;
                        __half* dl = (which == 1) ? g_kl : g_vl;
                        *reinterpret_cast<uint32_t*>(dh + off) = pack_hi2(v0, v1);
                        *reinterpret_cast<uint32_t*>(dl + off) = pack_lo2(v0, v1);
                    }
                } else {
                    *reinterpret_cast<float2*>(out + (size_t)m * EMBED + e)
                        = make_float2(v0, v1);
                }
            }
        }
    }
}

// ---------------------------------------------------------------------------
// Flash attention — R6 structure, fp16 2-product: S = Qh*(Kh+Kl), O += Ph*(Vh+Vl)
// ---------------------------------------------------------------------------
#define ABT 128
#define ABS 64
#define NBLK (T_LEN / ABS)   // 16
#define AQ_H   0
#define AST0   16384
#define S_KH    0
#define S_KL    8192
#define S_VH    16384
#define S_VL    24576
#define S_BIAS  32768
#define BIAS_ST 68
#define S_KPM   (32768 + 128 * BIAS_ST * 4)   // 67584
#define AST_STRIDE (S_KPM + 256)              // 67840
#define ATTN_SMEM (AST0 + 2 * AST_STRIDE)     // 152064

__global__ __launch_bounds__(256, 1)
void attn_mma_kernel(const int*   __restrict__ kpm,
                     const float* __restrict__ attn_mask,
                     const float* __restrict__ attn_bias)
{
    extern __shared__ char smc[];
    const uint32_t sb = s2u(smc);
    const int tid = threadIdx.x, lane = tid & 31, wid = tid >> 5;
    const int n = blockIdx.y, t0 = blockIdx.x * ABT;
    const int b = n >> 4, h = n & 15;
    const int wr0 = wid * 16;
    const int g = lane >> 2, qr = lane & 3;
    const int*   kpmg = kpm + b * T_LEN;
    const size_t nbase = (size_t)n << 16;
    const float* biasg = attn_bias + (size_t)n * T_LEN * T_LEN;

    auto load_kv_stage = [&](int blk) {
        const int s0 = blk * ABS;
        const uint32_t B = sb + AST0 + (uint32_t)(blk & 1) * AST_STRIDE;
#pragma unroll
        for (int it = 0; it < 2; it++) {
            int idx = it * 256 + tid;
            int row = idx >> 3, c = idx & 7;
            uint32_t so = sw128(row * 128 + c * 16);
            size_t go = nbase + (size_t)(s0 + row) * 64 + c * 8;
            cp_async16(B + S_KH + so, g_kh + go);
            cp_async16(B + S_KL + so, g_kl + go);
            cp_async16(B + S_VH + so, g_vh + go);
            cp_async16(B + S_VL + so, g_vl + go);
        }
#pragma unroll
        for (int it = 0; it < 8; it++) {
            int idx = it * 256 + tid;
            int row = idx >> 4, c = idx & 15;
            cp_async16(B + S_BIAS + row * (BIAS_ST * 4) + c * 16,
                       biasg + (size_t)(t0 + row) * T_LEN + s0 + c * 4);
        }
        if (tid < 16) cp_async16(B + S_KPM + tid * 16, kpmg + s0 + tid * 4);
    };

    // --- prologue: Q(hi) + stage 0 ---
    {
        const __half* Qh = g_qh + nbase + (size_t)t0 * 64;
#pragma unroll
        for (int it = 0; it < 4; it++) {
            int idx = it * 256 + tid;
            int row = idx >> 3, c = idx & 7;
            uint32_t so = sw128(row * 128 + c * 16);
            cp_async16(sb + AQ_H + so, Qh + row * 64 + c * 8);
        }
        load_kv_stage(0);
        cp_commit();
    }

    float m0 = -1e30f, m1 = -1e30f, l0 = 0.f, l1 = 0.f;
    float O[8][4];
#pragma unroll
    for (int i = 0; i < 8; i++)
#pragma unroll
        for (int q = 0; q < 4; q++) O[i][q] = 0.f;
    uint32_t qfh[4][4];

    const int tr0 = t0 + wr0 + g, tr1 = tr0 + 8;
    const int tl0 = wr0 + g;

    for (int blk = 0; blk < NBLK; blk++) {
        // mask prefetch to regs
        float2 mk0[8], mk1[8];
        {
            const int s0g = blk * ABS;
#pragma unroll
            for (int nf = 0; nf < 8; nf++) {
                const int scol = s0g + nf * 8 + qr * 2;
                mk0[nf] = __ldg(reinterpret_cast<const float2*>(attn_mask + (size_t)tr0 * T_LEN + scol));
                mk1[nf] = __ldg(reinterpret_cast<const float2*>(attn_mask + (size_t)tr1 * T_LEN + scol));
            }
        }
        if (blk + 1 < NBLK) {
            load_kv_stage(blk + 1);
            cp_commit();
            cp_wait<1>();
        } else {
            cp_wait<0>();
        }
        __syncthreads();

        if (blk == 0) {
#pragma unroll
            for (int ks = 0; ks < 4; ks++) {
                uint32_t aoff = sw128((uint32_t)(wr0 + (lane & 15)) * 128 +
                                      (uint32_t)(ks * 16 + (lane >> 4) * 8) * 2);
                ldm_x4(qfh[ks], sb + AQ_H + aoff);
            }
        }

        const uint32_t B = sb + AST0 + (uint32_t)(blk & 1) * AST_STRIDE;

        // ---- S = Qh (Kh + Kl) ----
        float S[8][4];
#pragma unroll
        for (int i = 0; i < 8; i++)
#pragma unroll
            for (int q = 0; q < 4; q++) S[i][q] = 0.f;
#pragma unroll
        for (int ks = 0; ks < 4; ks++) {
#pragma unroll
            for (int nf = 0; nf < 8; nf++) {
                uint32_t boff = sw128((uint32_t)(nf * 8 + (lane & 7)) * 128 +
                                      (uint32_t)(ks * 16 + ((lane >> 3) & 1) * 8) * 2);
                uint32_t kh[2], kl[2];
                ldm_x2(kh, B + S_KH + boff);
                ldm_x2(kl, B + S_KL + boff);
                mma16816(S[nf], qfh[ks], kh);
                mma16816(S[nf], qfh[ks], kl);
            }
        }

        // ---- mask(reg) + bias(smem) + kpm(smem), row max ----
        const int*   kpms   = (const int*)(smc + AST0 + (size_t)(blk & 1) * AST_STRIDE + S_KPM);
        const float* bias_s = (const float*)(smc + AST0 + (size_t)(blk & 1) * AST_STRIDE + S_BIAS);
        float rmax0 = -1e30f, rmax1 = -1e30f;
#pragma unroll
        for (int nf = 0; nf < 8; nf++) {
            const int sloc = nf * 8 + qr * 2;
            const int k0 = kpms[sloc], k1 = kpms[sloc + 1];
            float2 ba = *reinterpret_cast<const float2*>(bias_s + (size_t)tl0 * BIAS_ST + sloc);
            float2 bb = *reinterpret_cast<const float2*>(bias_s + (size_t)(tl0 + 8) * BIAS_ST + sloc);
            S[nf][0] = k0 ? -1e30f : S[nf][0] + mk0[nf].x + ba.x;
            S[nf][1] = k1 ? -1e30f : S[nf][1] + mk0[nf].y + ba.y;
            S[nf][2] = k0 ? -1e30f : S[nf][2] + mk1[nf].x + bb.x;
            S[nf][3] = k1 ? -1e30f : S[nf][3] + mk1[nf].y + bb.y;
            rmax0 = fmaxf(rmax0, fmaxf(S[nf][0], S[nf][1]));
            rmax1 = fmaxf(rmax1, fmaxf(S[nf][2], S[nf][3]));
        }
        rmax0 = fmaxf(rmax0, __shfl_xor_sync(0xffffffffu, rmax0, 1));
        rmax0 = fmaxf(rmax0, __shfl_xor_sync(0xffffffffu, rmax0, 2));
        rmax1 = fmaxf(rmax1, __shfl_xor_sync(0xffffffffu, rmax1, 1));
        rmax1 = fmaxf(rmax1, __shfl_xor_sync(0xffffffffu, rmax1, 2));

        const float mn0 = fmaxf(m0, rmax0), mn1 = fmaxf(m1, rmax1);
        const float es0 = __expf(m0 - mn0), es1 = __expf(m1 - mn1);
        m0 = mn0; m1 = mn1;

        float rs0 = 0.f, rs1 = 0.f;
#pragma unroll
        for (int nf = 0; nf < 8; nf++) {
            S[nf][0] = __expf(S[nf][0] - mn0);
            S[nf][1] = __expf(S[nf][1] - mn0);
            S[nf][2] = __expf(S[nf][2] - mn1);
            S[nf][3] = __expf(S[nf][3] - mn1);
            rs0 += S[nf][0] + S[nf][1];
            rs1 += S[nf][2] + S[nf][3];
        }
        rs0 += __shfl_xor_sync(0xffffffffu, rs0, 1);
        rs0 += __shfl_xor_sync(0xffffffffu, rs0, 2);
        rs1 += __shfl_xor_sync(0xffffffffu, rs1, 1);
        rs1 += __shfl_xor_sync(0xffffffffu, rs1, 2);
        l0 = l0 * es0 + rs0;
        l1 = l1 * es1 + rs1;

#pragma unroll
        for (int i = 0; i < 8; i++) {
            O[i][0] *= es0; O[i][1] *= es0;
            O[i][2] *= es1; O[i][3] *= es1;
        }

        // ---- O += Ph (Vh + Vl) ----
#pragma unroll
        for (int kp = 0; kp < 4; kp++) {
            uint32_t ah[4];
            ah[0] = pack_hi2(S[2*kp][0],   S[2*kp][1]);
            ah[1] = pack_hi2(S[2*kp][2],   S[2*kp][3]);
            ah[2] = pack_hi2(S[2*kp+1][0], S[2*kp+1][1]);
            ah[3] = pack_hi2(S[2*kp+1][2], S[2*kp+1][3]);
#pragma unroll
            for (int nf2 = 0; nf2 < 8; nf2++) {
                uint32_t voff = sw128((uint32_t)(kp * 16 + (lane & 15)) * 128 +
                                      (uint32_t)nf2 * 16);
                uint32_t vh[2], vl[2];
                ldm_x2_trans(vh, B + S_VH + voff);
                ldm_x2_trans(vl, B + S_VL + voff);
                mma16816(O[nf2], ah, vh);
                mma16816(O[nf2], ah, vl);
            }
        }
        __syncthreads();
    }

    // ---- normalize + write fp16 hi ----
    const float inv0 = 1.f / l0, inv1 = 1.f / l1;
    const size_t base0 = ((size_t)tr0 * BSZ + b) * EMBED + h * 64;
    const size_t base1 = ((size_t)tr1 * BSZ + b) * EMBED + h * 64;
#pragma unroll
    for (int nf2 = 0; nf2 < 8; nf2++) {
        const int d0 = nf2 * 8 + qr * 2;
        float v0 = O[nf2][0] * inv0, v1 = O[nf2][1] * inv0;
        float w0 = O[nf2][2] * inv1, w1 = O[nf2][3] * inv1;
        *reinterpret_cast<uint32_t*>(g_attnh + base0 + d0) = pack_hi2(v0, v1);
        *reinterpret_cast<uint32_t*>(g_attnh + base1 + d0) = pack_hi2(w0, w1);
    }
}

// ---------------------------------------------------------------------------
extern "C" void kernel_launch(void* const* d_in, const int* in_sizes, int n_in,
                              void* d_out, int out_size)
{
    const float* query     = (const float*)d_in[0];
    const int*   kpm       = (const int*)  d_in[1];
    const float* attn_mask = (const float*)d_in[2];
    const float* attn_bias = (const float*)d_in[3];
    const float* W_in      = (const float*)d_in[4];
    const float* b_in      = (const float*)d_in[5];
    const float* W_out     = (const float*)d_in[6];
    const float* b_out     = (const float*)d_in[7];
    float*       out       = (float*)d_out;

    static bool attr_set = false;
    if (!attr_set) {
        cudaFuncSetAttribute(gemm_mma, cudaFuncAttributeMaxDynamicSharedMemorySize, GEMM_SMEM);
        cudaFuncSetAttribute(attn_mma_kernel, cudaFuncAttributeMaxDynamicSharedMemorySize, ATTN_SMEM);
        attr_set = true;
    }

    __half *Ah, *Al, *Bh, *Bl, *ATh;
    cudaGetSymbolAddress((void**)&Ah, g_Ah);
    cudaGetSymbolAddress((void**)&Al, g_Al);
    cudaGetSymbolAddress((void**)&Bh, g_Bh);
    cudaGetSymbolAddress((void**)&Bl, g_Bl);
    cudaGetSymbolAddress((void**)&ATh, g_attnh);

    // 1) split query (hi used) and W_in (hi+lo used) to fp16 pairs
    split_kernel<<<MROWS * EMBED / 4 / 256, 256>>>(query, Ah, Al, MROWS * EMBED / 4);
    split_kernel<<<3 * EMBED * EMBED / 4 / 256, 256>>>(W_in, Bh, Bl, 3 * EMBED * EMBED / 4);

    // 2) QKV projection -> fp16 q(hi), k(hi/lo), v(hi/lo)
    {
        dim3 grid(3 * EMBED / TN, MROWS / TM);   // (24, 32)
        gemm_mma<<<grid, 256, GEMM_SMEM>>>(Ah, Bh, Bl, b_in, 0, nullptr);
    }

    // 3) Flash attention -> fp16 attn (hi)
    {
        dim3 grid(T_LEN / ABT, NBH);   // (8, 64)
        attn_mma_kernel<<<grid, 256, ATTN_SMEM>>>(kpm, attn_mask, attn_bias);
    }

    // 4) split W_out; output projection (A = attn fp16 hi)
    split_kernel<<<EMBED * EMBED / 4 / 256, 256>>>(W_out, Bh, Bl, EMBED * EMBED / 4);
    {
        dim3 grid(EMBED / TN, MROWS / TM);       // (8, 32)
        gemm_mma<<<grid, 256, GEMM_SMEM>>>(ATh, Bh, Bl, b_out, 1, out);
    }
}

// round 11
// speedup vs baseline: 2.2962x; 1.1618x over previous
#include <cuda_runtime.h>
#include <cuda_fp16.h>
#include <cstdint>

// Problem constants
#define T_LEN   1024
#define BSZ     4
#define EMBED   1024
#define NHEADS  16
#define HDIM    64
#define NBH     (BSZ * NHEADS)      // 64
#define MROWS   (T_LEN * BSZ)       // 4096
#define SCALING 0.125f

// fp16 scratch (hi only for q/k/v/attn)
__device__ __half g_qh[NBH * T_LEN * HDIM];
__device__ __half g_kh[NBH * T_LEN * HDIM];
__device__ __half g_vh[NBH * T_LEN * HDIM];
__device__ __half g_attnh[MROWS * EMBED];
// fp16 split GEMM operands (A hi only used; B hi+lo)
__device__ __half g_Ah[MROWS * EMBED];
__device__ __half g_Al[MROWS * EMBED];
__device__ __half g_Bh[3 * EMBED * EMBED];
__device__ __half g_Bl[3 * EMBED * EMBED];

// ---------------------------------------------------------------------------
// PTX helpers
// ---------------------------------------------------------------------------
__device__ __forceinline__ uint32_t s2u(const void* p) {
    return (uint32_t)__cvta_generic_to_shared(p);
}
__device__ __forceinline__ void cp_async16(uint32_t dst, const void* src) {
    asm volatile("cp.async.cg.shared.global [%0], [%1], 16;\n" :: "r"(dst), "l"(src));
}
__device__ __forceinline__ void cp_commit() {
    asm volatile("cp.async.commit_group;\n");
}
template<int N>
__device__ __forceinline__ void cp_wait() {
    asm volatile("cp.async.wait_group %0;\n" :: "n"(N));
}
__device__ __forceinline__ void ldm_x4(uint32_t* r, uint32_t addr) {
    asm volatile("ldmatrix.sync.aligned.m8n8.x4.shared.b16 {%0,%1,%2,%3}, [%4];"
                 : "=r"(r[0]), "=r"(r[1]), "=r"(r[2]), "=r"(r[3]) : "r"(addr));
}
__device__ __forceinline__ void ldm_x4_trans(uint32_t* r, uint32_t addr) {
    asm volatile("ldmatrix.sync.aligned.m8n8.x4.trans.shared.b16 {%0,%1,%2,%3}, [%4];"
                 : "=r"(r[0]), "=r"(r[1]), "=r"(r[2]), "=r"(r[3]) : "r"(addr));
}
// fp16 MMA, fp32 accumulate
__device__ __forceinline__ void mma16816(float* c, const uint32_t* a, const uint32_t* b) {
    asm volatile("mma.sync.aligned.m16n8k16.row.col.f32.f16.f16.f32 "
                 "{%0,%1,%2,%3}, {%4,%5,%6,%7}, {%8,%9}, {%0,%1,%2,%3};"
                 : "+f"(c[0]), "+f"(c[1]), "+f"(c[2]), "+f"(c[3])
                 : "r"(a[0]), "r"(a[1]), "r"(a[2]), "r"(a[3]), "r"(b[0]), "r"(b[1]));
}
__device__ __host__ __forceinline__ uint32_t sw128(uint32_t off) {
    return off ^ ((off >> 3) & 0x70);
}
__device__ __forceinline__ uint32_t pack_hi2(float a, float b) {
    __half2 t; t.x = __float2half_rn(a); t.y = __float2half_rn(b);
    uint32_t r; memcpy(&r, &t, 4); return r;
}
__device__ __forceinline__ uint32_t pack_lo2(float a, float b) {
    __half ha = __float2half_rn(a), hb = __float2half_rn(b);
    __half2 t;
    t.x = __float2half_rn(a - __half2float(ha));
    t.y = __float2half_rn(b - __half2float(hb));
    uint32_t r; memcpy(&r, &t, 4); return r;
}

// ---------------------------------------------------------------------------
// fp32 -> (hi, lo) fp16 split
// ---------------------------------------------------------------------------
__global__ __launch_bounds__(256)
void split_kernel(const float* __restrict__ src, __half* __restrict__ hi,
                  __half* __restrict__ lo, int n4)
{
    int i = blockIdx.x * 256 + threadIdx.x;
    if (i >= n4) return;
    float4 v = reinterpret_cast<const float4*>(src)[i];
    reinterpret_cast<uint32_t*>(hi)[2 * i]     = pack_hi2(v.x, v.y);
    reinterpret_cast<uint32_t*>(hi)[2 * i + 1] = pack_hi2(v.z, v.w);
    reinterpret_cast<uint32_t*>(lo)[2 * i]     = pack_lo2(v.x, v.y);
    reinterpret_cast<uint32_t*>(lo)[2 * i + 1] = pack_lo2(v.z, v.w);
}

// ---------------------------------------------------------------------------
// mma.sync fp16 2-product GEMM: D = Ah*(Bh+Bl). x4 B-frag loads (R7-verified).
// 256 threads, 8 warps x (64x32), 2-stage cp.async (60KB smem).
// ---------------------------------------------------------------------------
#define GK 1024
#define TM 128
#define TN 128
#define TBK 32
#define NKS (GK / TBK)
#define A_ST 40
#define TILE_B (128 * A_ST * 2)     // 10240
#define STAGE_B (3 * TILE_B)        // Ah, Bh, Bl
#define GEMM_SMEM (2 * STAGE_B)     // 61440

__device__ __forceinline__ void load_stage(uint32_t sbase,
    const __half* __restrict__ Ah,
    const __half* __restrict__ Bh, const __half* __restrict__ Bl,
    int row0, int col0, int k0, int tid)
{
#pragma unroll
    for (int it = 0; it < 2; it++) {
        int idx = it * 256 + tid;
        int r = idx >> 2, c = idx & 3;
        uint32_t so = r * (A_ST * 2) + c * 16;
        size_t ga = (size_t)(row0 + r) * GK + k0 + c * 8;
        size_t gb = (size_t)(col0 + r) * GK + k0 + c * 8;
        cp_async16(sbase + 0 * TILE_B + so, Ah + ga);
        cp_async16(sbase + 1 * TILE_B + so, Bh + gb);
        cp_async16(sbase + 2 * TILE_B + so, Bl + gb);
    }
}

__global__ __launch_bounds__(256)
void gemm_mma(const __half* __restrict__ Ah,
              const __half* __restrict__ Bh, const __half* __restrict__ Bl,
              const float* __restrict__ bias, int mode, float* __restrict__ out)
{
    extern __shared__ char smc[];
    const uint32_t sb = s2u(smc);
    const int tid  = threadIdx.x;
    const int lane = tid & 31;
    const int wid  = tid >> 5;
    const int wr = wid & 1;
    const int wc = wid >> 1;
    const int row0 = blockIdx.y * TM, col0 = blockIdx.x * TN;

    const int a_row = lane & 15;
    const int a_k8  = (lane >> 4) * 8;
    // x4 B-frag addressing (R7-verified)
    const int b_mat = lane >> 3;
    const int b_nf_off = b_mat >> 1;
    const int b_k8  = (b_mat & 1) * 8;
    const int b_row = lane & 7;

    float acc[4][4][4];
#pragma unroll
    for (int i = 0; i < 4; i++)
#pragma unroll
        for (int j = 0; j < 4; j++)
#pragma unroll
            for (int q = 0; q < 4; q++) acc[i][j][q] = 0.f;

    load_stage(sb, Ah, Bh, Bl, row0, col0, 0, tid);
    cp_commit();

    for (int ks = 0; ks < NKS; ks++) {
        const uint32_t cur = sb + (uint32_t)(ks & 1) * STAGE_B;
        if (ks + 1 < NKS) {
            load_stage(sb + (uint32_t)((ks + 1) & 1) * STAGE_B,
                       Ah, Bh, Bl, row0, col0, (ks + 1) * TBK, tid);
            cp_commit();
            cp_wait<1>();
        } else {
            cp_wait<0>();
        }
        __syncthreads();

#pragma unroll
        for (int kk = 0; kk < 2; kk++) {
            const int k0 = kk * 16;
            uint32_t afh[4][4];
#pragma unroll
            for (int mf = 0; mf < 4; mf++) {
                uint32_t aoff = (uint32_t)((wr * 64 + mf * 16 + a_row) * A_ST + k0 + a_k8) * 2;
                ldm_x4(afh[mf], cur + 0 * TILE_B + aoff);
            }
            uint32_t bfh[2][4], bfl[2][4];
#pragma unroll
            for (int nfp = 0; nfp < 2; nfp++) {
                uint32_t boff = (uint32_t)((wc * 32 + (2 * nfp + b_nf_off) * 8 + b_row) * A_ST
                                           + k0 + b_k8) * 2;
                ldm_x4(bfh[nfp], cur + 1 * TILE_B + boff);
                ldm_x4(bfl[nfp], cur + 2 * TILE_B + boff);
            }
#pragma unroll
            for (int mf = 0; mf < 4; mf++)
#pragma unroll
                for (int nfp = 0; nfp < 2; nfp++)
#pragma unroll
                    for (int half = 0; half < 2; half++) {
                        const int nf = 2 * nfp + half;
                        mma16816(acc[mf][nf], afh[mf], bfh[nfp] + half * 2);
                        mma16816(acc[mf][nf], afh[mf], bfl[nfp] + half * 2);
                    }
        }
        __syncthreads();
    }

    const int g = lane >> 2, tig = lane & 3;
#pragma unroll
    for (int nf = 0; nf < 4; nf++) {
        const int e = col0 + wc * 32 + nf * 8 + tig * 2;
        const float bz0 = __ldg(bias + e);
        const float bz1 = __ldg(bias + e + 1);
#pragma unroll
        for (int mf = 0; mf < 4; mf++) {
#pragma unroll
            for (int half = 0; half < 2; half++) {
                const int m = row0 + wr * 64 + mf * 16 + g + half * 8;
                float v0 = acc[mf][nf][half * 2 + 0] + bz0;
                float v1 = acc[mf][nf][half * 2 + 1] + bz1;
                if (mode == 0) {
                    const int t = m >> 2, b = m & 3;
                    const int which = e >> 10;
                    const int rem = e & 1023;
                    const int h = rem >> 6, d = rem & 63;
                    const int n = (b << 4) + h;
                    size_t off = ((size_t)n << 16) + ((size_t)t << 6) + d;
                    if (which == 0) { v0 *= SCALING; v1 *= SCALING; }
                    __half* dh = (which == 0) ? g_qh : (which == 1) ? g_kh : g_vh;
                    *reinterpret_cast<uint32_t*>(dh + off) = pack_hi2(v0, v1);
                } else {
                    *reinterpret_cast<float2*>(out + (size_t)m * EMBED + e)
                        = make_float2(v0, v1);
                }
            }
        }
    }
}

// ---------------------------------------------------------------------------
// Flash attention — fp16 single-product S and PV, x4 ldmatrix (R7-verified).
// CTA = 128 q-rows x head; 8 warps; key blocks of 64; 2 smem stages.
// ---------------------------------------------------------------------------
#define ABT 128
#define ABS 64
#define NBLK (T_LEN / ABS)   // 16
#define AQ_H   0
#define AST0   16384
#define S_KH    0
#define S_VH    8192
#define S_BIAS  16384
#define BIAS_ST 68
#define S_KPM   (16384 + 128 * BIAS_ST * 4)   // 51200
#define AST_STRIDE (S_KPM + 256)              // 51456
#define ATTN_SMEM (AST0 + 2 * AST_STRIDE)     // 119296

__global__ __launch_bounds__(256, 1)
void attn_mma_kernel(const int*   __restrict__ kpm,
                     const float* __restrict__ attn_mask,
                     const float* __restrict__ attn_bias)
{
    extern __shared__ char smc[];
    const uint32_t sb = s2u(smc);
    const int tid = threadIdx.x, lane = tid & 31, wid = tid >> 5;
    const int n = blockIdx.y, t0 = blockIdx.x * ABT;
    const int b = n >> 4, h = n & 15;
    const int wr0 = wid * 16;
    const int g = lane >> 2, qr = lane & 3;
    const int*   kpmg = kpm + b * T_LEN;
    const size_t nbase = (size_t)n << 16;
    const float* biasg = attn_bias + (size_t)n * T_LEN * T_LEN;

    auto load_kv_stage = [&](int blk) {
        const int s0 = blk * ABS;
        const uint32_t B = sb + AST0 + (uint32_t)(blk & 1) * AST_STRIDE;
        // K,V hi: 2 arrays x 64 rows x 8 chunks = 1024 chunks -> 4/thread
#pragma unroll
        for (int it = 0; it < 2; it++) {
            int idx = it * 256 + tid;
            int row = idx >> 3, c = idx & 7;
            uint32_t so = sw128(row * 128 + c * 16);
            size_t go = nbase + (size_t)(s0 + row) * 64 + c * 8;
            cp_async16(B + S_KH + so, g_kh + go);
            cp_async16(B + S_VH + so, g_vh + go);
        }
#pragma unroll
        for (int it = 0; it < 8; it++) {
            int idx = it * 256 + tid;
            int row = idx >> 4, c = idx & 15;
            cp_async16(B + S_BIAS + row * (BIAS_ST * 4) + c * 16,
                       biasg + (size_t)(t0 + row) * T_LEN + s0 + c * 4);
        }
        if (tid < 16) cp_async16(B + S_KPM + tid * 16, kpmg + s0 + tid * 4);
    };

    // --- prologue: Q(hi) + stage 0 ---
    {
        const __half* Qh = g_qh + nbase + (size_t)t0 * 64;
#pragma unroll
        for (int it = 0; it < 4; it++) {
            int idx = it * 256 + tid;
            int row = idx >> 3, c = idx & 7;
            uint32_t so = sw128(row * 128 + c * 16);
            cp_async16(sb + AQ_H + so, Qh + row * 64 + c * 8);
        }
        load_kv_stage(0);
        cp_commit();
    }

    float m0 = -1e30f, m1 = -1e30f, l0 = 0.f, l1 = 0.f;
    float O[8][4];
#pragma unroll
    for (int i = 0; i < 8; i++)
#pragma unroll
        for (int q = 0; q < 4; q++) O[i][q] = 0.f;
    uint32_t qfh[4][4];

    const int tr0 = t0 + wr0 + g, tr1 = tr0 + 8;
    const int tl0 = wr0 + g;

    // x4 K addressing (R7-verified)
    const int k_mat = lane >> 3;
    const int k_nf_off = k_mat >> 1;
    const int k_k8 = (k_mat & 1) * 8;
    const int k_row = lane & 7;
    // x4 V addressing (trans, R7-verified)
    const int v_blk = lane >> 4;
    const int v_row = lane & 15;

    for (int blk = 0; blk < NBLK; blk++) {
        // mask prefetch to regs
        float2 mk0[8], mk1[8];
        {
            const int s0g = blk * ABS;
#pragma unroll
            for (int nf = 0; nf < 8; nf++) {
                const int scol = s0g + nf * 8 + qr * 2;
                mk0[nf] = __ldg(reinterpret_cast<const float2*>(attn_mask + (size_t)tr0 * T_LEN + scol));
                mk1[nf] = __ldg(reinterpret_cast<const float2*>(attn_mask + (size_t)tr1 * T_LEN + scol));
            }
        }
        if (blk + 1 < NBLK) {
            load_kv_stage(blk + 1);
            cp_commit();
            cp_wait<1>();
        } else {
            cp_wait<0>();
        }
        __syncthreads();

        if (blk == 0) {
#pragma unroll
            for (int ks = 0; ks < 4; ks++) {
                uint32_t aoff = sw128((uint32_t)(wr0 + (lane & 15)) * 128 +
                                      (uint32_t)(ks * 16 + (lane >> 4) * 8) * 2);
                ldm_x4(qfh[ks], sb + AQ_H + aoff);
            }
        }

        const uint32_t B = sb + AST0 + (uint32_t)(blk & 1) * AST_STRIDE;

        // ---- S = Qh Kh (x4 K loads) ----
        float S[8][4];
#pragma unroll
        for (int i = 0; i < 8; i++)
#pragma unroll
            for (int q = 0; q < 4; q++) S[i][q] = 0.f;
#pragma unroll
        for (int ks = 0; ks < 4; ks++) {
#pragma unroll
            for (int nfp = 0; nfp < 4; nfp++) {
                uint32_t boff = sw128((uint32_t)((2 * nfp + k_nf_off) * 8 + k_row) * 128 +
                                      (uint32_t)(ks * 16 + k_k8) * 2);
                uint32_t kh[4];
                ldm_x4(kh, B + S_KH + boff);
                mma16816(S[2 * nfp + 0], qfh[ks], kh);
                mma16816(S[2 * nfp + 1], qfh[ks], kh + 2);
            }
        }

        // ---- mask(reg) + bias(smem) + kpm(smem), row max ----
        const int*   kpms   = (const int*)(smc + AST0 + (size_t)(blk & 1) * AST_STRIDE + S_KPM);
        const float* bias_s = (const float*)(smc + AST0 + (size_t)(blk & 1) * AST_STRIDE + S_BIAS);
        float rmax0 = -1e30f, rmax1 = -1e30f;
#pragma unroll
        for (int nf = 0; nf < 8; nf++) {
            const int sloc = nf * 8 + qr * 2;
            const int k0 = kpms[sloc], k1 = kpms[sloc + 1];
            float2 ba = *reinterpret_cast<const float2*>(bias_s + (size_t)tl0 * BIAS_ST + sloc);
            float2 bb = *reinterpret_cast<const float2*>(bias_s + (size_t)(tl0 + 8) * BIAS_ST + sloc);
            S[nf][0] = k0 ? -1e30f : S[nf][0] + mk0[nf].x + ba.x;
            S[nf][1] = k1 ? -1e30f : S[nf][1] + mk0[nf].y + ba.y;
            S[nf][2] = k0 ? -1e30f : S[nf][2] + mk1[nf].x + bb.x;
            S[nf][3] = k1 ? -1e30f : S[nf][3] + mk1[nf].y + bb.y;
            rmax0 = fmaxf(rmax0, fmaxf(S[nf][0], S[nf][1]));
            rmax1 = fmaxf(rmax1, fmaxf(S[nf][2], S[nf][3]));
        }
        rmax0 = fmaxf(rmax0, __shfl_xor_sync(0xffffffffu, rmax0, 1));
        rmax0 = fmaxf(rmax0, __shfl_xor_sync(0xffffffffu, rmax0, 2));
        rmax1 = fmaxf(rmax1, __shfl_xor_sync(0xffffffffu, rmax1, 1));
        rmax1 = fmaxf(rmax1, __shfl_xor_sync(0xffffffffu, rmax1, 2));

        const float mn0 = fmaxf(m0, rmax0), mn1 = fmaxf(m1, rmax1);
        const float es0 = __expf(m0 - mn0), es1 = __expf(m1 - mn1);
        m0 = mn0; m1 = mn1;

        float rs0 = 0.f, rs1 = 0.f;
#pragma unroll
        for (int nf = 0; nf < 8; nf++) {
            S[nf][0] = __expf(S[nf][0] - mn0);
            S[nf][1] = __expf(S[nf][1] - mn0);
            S[nf][2] = __expf(S[nf][2] - mn1);
            S[nf][3] = __expf(S[nf][3] - mn1);
            rs0 += S[nf][0] + S[nf][1];
            rs1 += S[nf][2] + S[nf][3];
        }
        rs0 += __shfl_xor_sync(0xffffffffu, rs0, 1);
        rs0 += __shfl_xor_sync(0xffffffffu, rs0, 2);
        rs1 += __shfl_xor_sync(0xffffffffu, rs1, 1);
        rs1 += __shfl_xor_sync(0xffffffffu, rs1, 2);
        l0 = l0 * es0 + rs0;
        l1 = l1 * es1 + rs1;

#pragma unroll
        for (int i = 0; i < 8; i++) {
            O[i][0] *= es0; O[i][1] *= es0;
            O[i][2] *= es1; O[i][3] *= es1;
        }

        // ---- O += Ph Vh (x4 trans V loads) ----
#pragma unroll
        for (int kp = 0; kp < 4; kp++) {
            uint32_t ah[4];
            ah[0] = pack_hi2(S[2*kp][0],   S[2*kp][1]);
            ah[1] = pack_hi2(S[2*kp][2],   S[2*kp][3]);
            ah[2] = pack_hi2(S[2*kp+1][0], S[2*kp+1][1]);
            ah[3] = pack_hi2(S[2*kp+1][2], S[2*kp+1][3]);
#pragma unroll
            for (int np = 0; np < 4; np++) {
                uint32_t voff = sw128((uint32_t)(kp * 16 + v_row) * 128 +
                                      (uint32_t)(2 * np + v_blk) * 16);
                uint32_t vh[4];
                ldm_x4_trans(vh, B + S_VH + voff);
                mma16816(O[2 * np + 0], ah, vh);
                mma16816(O[2 * np + 1], ah, vh + 2);
            }
        }
        __syncthreads();
    }

    // ---- normalize + write fp16 hi ----
    const float inv0 = 1.f / l0, inv1 = 1.f / l1;
    const size_t base0 = ((size_t)tr0 * BSZ + b) * EMBED + h * 64;
    const size_t base1 = ((size_t)tr1 * BSZ + b) * EMBED + h * 64;
#pragma unroll
    for (int nf2 = 0; nf2 < 8; nf2++) {
        const int d0 = nf2 * 8 + qr * 2;
        float v0 = O[nf2][0] * inv0, v1 = O[nf2][1] * inv0;
        float w0 = O[nf2][2] * inv1, w1 = O[nf2][3] * inv1;
        *reinterpret_cast<uint32_t*>(g_attnh + base0 + d0) = pack_hi2(v0, v1);
        *reinterpret_cast<uint32_t*>(g_attnh + base1 + d0) = pack_hi2(w0, w1);
    }
}

// ---------------------------------------------------------------------------
extern "C" void kernel_launch(void* const* d_in, const int* in_sizes, int n_in,
                              void* d_out, int out_size)
{
    const float* query     = (const float*)d_in[0];
    const int*   kpm       = (const int*)  d_in[1];
    const float* attn_mask = (const float*)d_in[2];
    const float* attn_bias = (const float*)d_in[3];
    const float* W_in      = (const float*)d_in[4];
    const float* b_in      = (const float*)d_in[5];
    const float* W_out     = (const float*)d_in[6];
    const float* b_out     = (const float*)d_in[7];
    float*       out       = (float*)d_out;

    static bool attr_set = false;
    if (!attr_set) {
        cudaFuncSetAttribute(gemm_mma, cudaFuncAttributeMaxDynamicSharedMemorySize, GEMM_SMEM);
        cudaFuncSetAttribute(attn_mma_kernel, cudaFuncAttributeMaxDynamicSharedMemorySize, ATTN_SMEM);
        attr_set = true;
    }

    __half *Ah, *Al, *Bh, *Bl, *ATh;
    cudaGetSymbolAddress((void**)&Ah, g_Ah);
    cudaGetSymbolAddress((void**)&Al, g_Al);
    cudaGetSymbolAddress((void**)&Bh, g_Bh);
    cudaGetSymbolAddress((void**)&Bl, g_Bl);
    cudaGetSymbolAddress((void**)&ATh, g_attnh);

    // 1) split query (hi used) and W_in (hi+lo) to fp16 pairs
    split_kernel<<<MROWS * EMBED / 4 / 256, 256>>>(query, Ah, Al, MROWS * EMBED / 4);
    split_kernel<<<3 * EMBED * EMBED / 4 / 256, 256>>>(W_in, Bh, Bl, 3 * EMBED * EMBED / 4);

    // 2) QKV projection -> fp16 q/k/v (hi only)
    {
        dim3 grid(3 * EMBED / TN, MROWS / TM);   // (24, 32)
        gemm_mma<<<grid, 256, GEMM_SMEM>>>(Ah, Bh, Bl, b_in, 0, nullptr);
    }

    // 3) Flash attention -> fp16 attn (hi)
    {
        dim3 grid(T_LEN / ABT, NBH);   // (8, 64)
        attn_mma_kernel<<<grid, 256, ATTN_SMEM>>>(kpm, attn_mask, attn_bias);
    }

    // 4) split W_out; output projection (A = attn fp16 hi)
    split_kernel<<<EMBED * EMBED / 4 / 256, 256>>>(W_out, Bh, Bl, EMBED * EMBED / 4);
    {
        dim3 grid(EMBED / TN, MROWS / TM);       // (8, 32)
        gemm_mma<<<grid, 256, GEMM_SMEM>>>(ATh, Bh, Bl, b_out, 1, out);
    }
}

// round 12
// speedup vs baseline: 2.3376x; 1.0180x over previous
#include <cuda_runtime.h>
#include <cuda_fp16.h>
#include <cstdint>

// Problem constants
#define T_LEN   1024
#define BSZ     4
#define EMBED   1024
#define NHEADS  16
#define HDIM    64
#define NBH     (BSZ * NHEADS)      // 64
#define MROWS   (T_LEN * BSZ)       // 4096
#define SCALING 0.125f
#define LOG2E   1.4426950408889634f

// fp16 scratch (hi only for q/k/v/attn); q carries SCALING*LOG2E
__device__ __half g_qh[NBH * T_LEN * HDIM];
__device__ __half g_kh[NBH * T_LEN * HDIM];
__device__ __half g_vh[NBH * T_LEN * HDIM];
__device__ __half g_attnh[MROWS * EMBED];
// fp16 split GEMM operands
__device__ __half g_Ah[MROWS * EMBED];
__device__ __half g_Bh[3 * EMBED * EMBED];
__device__ __half g_Bl[3 * EMBED * EMBED];
// mask + key-padding folded, per batch: (B, T, S)
__device__ float g_maskb[BSZ * T_LEN * T_LEN];   // 16 MB

// ---------------------------------------------------------------------------
// PTX helpers
// ---------------------------------------------------------------------------
__device__ __forceinline__ uint32_t s2u(const void* p) {
    return (uint32_t)__cvta_generic_to_shared(p);
}
__device__ __forceinline__ void cp_async16(uint32_t dst, const void* src) {
    asm volatile("cp.async.cg.shared.global [%0], [%1], 16;\n" :: "r"(dst), "l"(src));
}
__device__ __forceinline__ void cp_commit() {
    asm volatile("cp.async.commit_group;\n");
}
template<int N>
__device__ __forceinline__ void cp_wait() {
    asm volatile("cp.async.wait_group %0;\n" :: "n"(N));
}
__device__ __forceinline__ void ldm_x4(uint32_t* r, uint32_t addr) {
    asm volatile("ldmatrix.sync.aligned.m8n8.x4.shared.b16 {%0,%1,%2,%3}, [%4];"
                 : "=r"(r[0]), "=r"(r[1]), "=r"(r[2]), "=r"(r[3]) : "r"(addr));
}
__device__ __forceinline__ void ldm_x4_trans(uint32_t* r, uint32_t addr) {
    asm volatile("ldmatrix.sync.aligned.m8n8.x4.trans.shared.b16 {%0,%1,%2,%3}, [%4];"
                 : "=r"(r[0]), "=r"(r[1]), "=r"(r[2]), "=r"(r[3]) : "r"(addr));
}
__device__ __forceinline__ void mma16816(float* c, const uint32_t* a, const uint32_t* b) {
    asm volatile("mma.sync.aligned.m16n8k16.row.col.f32.f16.f16.f32 "
                 "{%0,%1,%2,%3}, {%4,%5,%6,%7}, {%8,%9}, {%0,%1,%2,%3};"
                 : "+f"(c[0]), "+f"(c[1]), "+f"(c[2]), "+f"(c[3])
                 : "r"(a[0]), "r"(a[1]), "r"(a[2]), "r"(a[3]), "r"(b[0]), "r"(b[1]));
}
__device__ __forceinline__ float ex2f(float x) {
    float y;
    asm("ex2.approx.ftz.f32 %0, %1;" : "=f"(y) : "f"(x));
    return y;
}
__device__ __host__ __forceinline__ uint32_t sw128(uint32_t off) {
    return off ^ ((off >> 3) & 0x70);
}
__device__ __forceinline__ uint32_t pack_hi2(float a, float b) {
    __half2 t; t.x = __float2half_rn(a); t.y = __float2half_rn(b);
    uint32_t r; memcpy(&r, &t, 4); return r;
}
__device__ __forceinline__ uint32_t pack_lo2(float a, float b) {
    __half ha = __float2half_rn(a), hb = __float2half_rn(b);
    __half2 t;
    t.x = __float2half_rn(a - __half2float(ha));
    t.y = __float2half_rn(b - __half2float(hb));
    uint32_t r; memcpy(&r, &t, 4); return r;
}

// ---------------------------------------------------------------------------
// Prep kernels
// ---------------------------------------------------------------------------
__global__ __launch_bounds__(256)
void split_kernel(const float* __restrict__ src, __half* __restrict__ hi,
                  __half* __restrict__ lo, int n4)
{
    int i = blockIdx.x * 256 + threadIdx.x;
    if (i >= n4) return;
    float4 v = reinterpret_cast<const float4*>(src)[i];
    reinterpret_cast<uint32_t*>(hi)[2 * i]     = pack_hi2(v.x, v.y);
    reinterpret_cast<uint32_t*>(hi)[2 * i + 1] = pack_hi2(v.z, v.w);
    reinterpret_cast<uint32_t*>(lo)[2 * i]     = pack_lo2(v.x, v.y);
    reinterpret_cast<uint32_t*>(lo)[2 * i + 1] = pack_lo2(v.z, v.w);
}

__global__ __launch_bounds__(256)
void split_hi_kernel(const float* __restrict__ src, __half* __restrict__ hi, int n4)
{
    int i = blockIdx.x * 256 + threadIdx.x;
    if (i >= n4) return;
    float4 v = reinterpret_cast<const float4*>(src)[i];
    reinterpret_cast<uint32_t*>(hi)[2 * i]     = pack_hi2(v.x, v.y);
    reinterpret_cast<uint32_t*>(hi)[2 * i + 1] = pack_hi2(v.z, v.w);
}

// mask_b[b][t][s] = mask[t][s] + (kpm[b][s] ? -1e30 : 0)
__global__ __launch_bounds__(256)
void prep_mask_kernel(const float* __restrict__ mask, const int* __restrict__ kpm)
{
    int i = blockIdx.x * 256 + threadIdx.x;        // over BSZ*T*T/4
    int idx = i * 4;
    int b = idx >> 20;
    int rem = idx & ((1 << 20) - 1);
    int t = rem >> 10;
    int s = rem & 1023;
    float4 m = *reinterpret_cast<const float4*>(mask + (size_t)t * T_LEN + s);
    const int* kp = kpm + b * T_LEN + s;
    float4 o;
    o.x = m.x + (kp[0] ? -1e30f : 0.f);
    o.y = m.y + (kp[1] ? -1e30f : 0.f);
    o.z = m.z + (kp[2] ? -1e30f : 0.f);
    o.w = m.w + (kp[3] ? -1e30f : 0.f);
    reinterpret_cast<float4*>(g_maskb)[i] = o;
}

// ---------------------------------------------------------------------------
// mma.sync fp16 2-product GEMM: D = Ah*(Bh+Bl). 2 CTAs/SM via launch bounds.
// ---------------------------------------------------------------------------
#define GK 1024
#define TM 128
#define TN 128
#define TBK 32
#define NKS (GK / TBK)
#define A_ST 40
#define TILE_B (128 * A_ST * 2)     // 10240
#define STAGE_B (3 * TILE_B)        // Ah, Bh, Bl
#define GEMM_SMEM (2 * STAGE_B)     // 61440

__device__ __forceinline__ void load_stage(uint32_t sbase,
    const __half* __restrict__ Ah,
    const __half* __restrict__ Bh, const __half* __restrict__ Bl,
    int row0, int col0, int k0, int tid)
{
#pragma unroll
    for (int it = 0; it < 2; it++) {
        int idx = it * 256 + tid;
        int r = idx >> 2, c = idx & 3;
        uint32_t so = r * (A_ST * 2) + c * 16;
        size_t ga = (size_t)(row0 + r) * GK + k0 + c * 8;
        size_t gb = (size_t)(col0 + r) * GK + k0 + c * 8;
        cp_async16(sbase + 0 * TILE_B + so, Ah + ga);
        cp_async16(sbase + 1 * TILE_B + so, Bh + gb);
        cp_async16(sbase + 2 * TILE_B + so, Bl + gb);
    }
}

__global__ __launch_bounds__(256, 2)
void gemm_mma(const __half* __restrict__ Ah,
              const __half* __restrict__ Bh, const __half* __restrict__ Bl,
              const float* __restrict__ bias, int mode, float* __restrict__ out)
{
    extern __shared__ char smc[];
    const uint32_t sb = s2u(smc);
    const int tid  = threadIdx.x;
    const int lane = tid & 31;
    const int wid  = tid >> 5;
    const int wr = wid & 1;
    const int wc = wid >> 1;
    const int row0 = blockIdx.y * TM, col0 = blockIdx.x * TN;

    const int a_row = lane & 15;
    const int a_k8  = (lane >> 4) * 8;
    const int b_mat = lane >> 3;
    const int b_nf_off = b_mat >> 1;
    const int b_k8  = (b_mat & 1) * 8;
    const int b_row = lane & 7;

    float acc[4][4][4];
#pragma unroll
    for (int i = 0; i < 4; i++)
#pragma unroll
        for (int j = 0; j < 4; j++)
#pragma unroll
            for (int q = 0; q < 4; q++) acc[i][j][q] = 0.f;

    load_stage(sb, Ah, Bh, Bl, row0, col0, 0, tid);
    cp_commit();

    for (int ks = 0; ks < NKS; ks++) {
        const uint32_t cur = sb + (uint32_t)(ks & 1) * STAGE_B;
        if (ks + 1 < NKS) {
            load_stage(sb + (uint32_t)((ks + 1) & 1) * STAGE_B,
                       Ah, Bh, Bl, row0, col0, (ks + 1) * TBK, tid);
            cp_commit();
            cp_wait<1>();
        } else {
            cp_wait<0>();
        }
        __syncthreads();

#pragma unroll
        for (int kk = 0; kk < 2; kk++) {
            const int k0 = kk * 16;
            uint32_t afh[4][4];
#pragma unroll
            for (int mf = 0; mf < 4; mf++) {
                uint32_t aoff = (uint32_t)((wr * 64 + mf * 16 + a_row) * A_ST + k0 + a_k8) * 2;
                ldm_x4(afh[mf], cur + 0 * TILE_B + aoff);
            }
            uint32_t bfh[2][4], bfl[2][4];
#pragma unroll
            for (int nfp = 0; nfp < 2; nfp++) {
                uint32_t boff = (uint32_t)((wc * 32 + (2 * nfp + b_nf_off) * 8 + b_row) * A_ST
                                           + k0 + b_k8) * 2;
                ldm_x4(bfh[nfp], cur + 1 * TILE_B + boff);
                ldm_x4(bfl[nfp], cur + 2 * TILE_B + boff);
            }
#pragma unroll
            for (int mf = 0; mf < 4; mf++)
#pragma unroll
                for (int nfp = 0; nfp < 2; nfp++)
#pragma unroll
                    for (int half = 0; half < 2; half++) {
                        const int nf = 2 * nfp + half;
                        mma16816(acc[mf][nf], afh[mf], bfh[nfp] + half * 2);
                        mma16816(acc[mf][nf], afh[mf], bfl[nfp] + half * 2);
                    }
        }
        __syncthreads();
    }

    const int g = lane >> 2, tig = lane & 3;
#pragma unroll
    for (int nf = 0; nf < 4; nf++) {
        const int e = col0 + wc * 32 + nf * 8 + tig * 2;
        const float bz0 = __ldg(bias + e);
        const float bz1 = __ldg(bias + e + 1);
#pragma unroll
        for (int mf = 0; mf < 4; mf++) {
#pragma unroll
            for (int half = 0; half < 2; half++) {
                const int m = row0 + wr * 64 + mf * 16 + g + half * 8;
                float v0 = acc[mf][nf][half * 2 + 0] + bz0;
                float v1 = acc[mf][nf][half * 2 + 1] + bz1;
                if (mode == 0) {
                    const int t = m >> 2, b = m & 3;
                    const int which = e >> 10;
                    const int rem = e & 1023;
                    const int h = rem >> 6, d = rem & 63;
                    const int n = (b << 4) + h;
                    size_t off = ((size_t)n << 16) + ((size_t)t << 6) + d;
                    if (which == 0) {
                        const float qs = SCALING * LOG2E;   // exp2-form softmax
                        v0 *= qs; v1 *= qs;
                    }
                    __half* dh = (which == 0) ? g_qh : (which == 1) ? g_kh : g_vh;
                    *reinterpret_cast<uint32_t*>(dh + off) = pack_hi2(v0, v1);
                } else {
                    *reinterpret_cast<float2*>(out + (size_t)m * EMBED + e)
                        = make_float2(v0, v1);
                }
            }
        }
    }
}

// ---------------------------------------------------------------------------
// Flash attention — exp2 softmax, mask_b (kpm folded), single-product fp16.
// ---------------------------------------------------------------------------
#define ABT 128
#define ABS 64
#define NBLK (T_LEN / ABS)   // 16
#define AQ_H   0
#define AST0   16384
#define S_KH    0
#define S_VH    8192
#define S_BIAS  16384
#define BIAS_ST 68
#define AST_STRIDE (16384 + 128 * BIAS_ST * 4)   // 51200
#define ATTN_SMEM (AST0 + 2 * AST_STRIDE)        // 118784

__global__ __launch_bounds__(256, 1)
void attn_mma_kernel(const float* __restrict__ attn_bias)
{
    extern __shared__ char smc[];
    const uint32_t sb = s2u(smc);
    const int tid = threadIdx.x, lane = tid & 31, wid = tid >> 5;
    const int n = blockIdx.y, t0 = blockIdx.x * ABT;
    const int b = n >> 4, h = n & 15;
    const int wr0 = wid * 16;
    const int g = lane >> 2, qr = lane & 3;
    const size_t nbase = (size_t)n << 16;
    const float* biasg = attn_bias + (size_t)n * T_LEN * T_LEN;
    const float* maskb = g_maskb + (size_t)b * T_LEN * T_LEN;

    auto load_kv_stage = [&](int blk) {
        const int s0 = blk * ABS;
        const uint32_t B = sb + AST0 + (uint32_t)(blk & 1) * AST_STRIDE;
#pragma unroll
        for (int it = 0; it < 2; it++) {
            int idx = it * 256 + tid;
            int row = idx >> 3, c = idx & 7;
            uint32_t so = sw128(row * 128 + c * 16);
            size_t go = nbase + (size_t)(s0 + row) * 64 + c * 8;
            cp_async16(B + S_KH + so, g_kh + go);
            cp_async16(B + S_VH + so, g_vh + go);
        }
#pragma unroll
        for (int it = 0; it < 8; it++) {
            int idx = it * 256 + tid;
            int row = idx >> 4, c = idx & 15;
            cp_async16(B + S_BIAS + row * (BIAS_ST * 4) + c * 16,
                       biasg + (size_t)(t0 + row) * T_LEN + s0 + c * 4);
        }
    };

    // --- prologue: Q(hi, pre-scaled by 0.125*log2e) + stage 0 ---
    {
        const __half* Qh = g_qh + nbase + (size_t)t0 * 64;
#pragma unroll
        for (int it = 0; it < 4; it++) {
            int idx = it * 256 + tid;
            int row = idx >> 3, c = idx & 7;
            uint32_t so = sw128(row * 128 + c * 16);
            cp_async16(sb + AQ_H + so, Qh + row * 64 + c * 8);
        }
        load_kv_stage(0);
        cp_commit();
    }

    float m0 = -1e30f, m1 = -1e30f, l0 = 0.f, l1 = 0.f;
    float O[8][4];
#pragma unroll
    for (int i = 0; i < 8; i++)
#pragma unroll
        for (int q = 0; q < 4; q++) O[i][q] = 0.f;
    uint32_t qfh[4][4];

    const int tr0 = t0 + wr0 + g, tr1 = tr0 + 8;
    const int tl0 = wr0 + g;

    const int k_mat = lane >> 3;
    const int k_nf_off = k_mat >> 1;
    const int k_k8 = (k_mat & 1) * 8;
    const int k_row = lane & 7;
    const int v_blk = lane >> 4;
    const int v_row = lane & 15;

    for (int blk = 0; blk < NBLK; blk++) {
        // mask_b prefetch to regs (kpm already folded in)
        float2 mk0[8], mk1[8];
        {
            const int s0g = blk * ABS;
#pragma unroll
            for (int nf = 0; nf < 8; nf++) {
                const int scol = s0g + nf * 8 + qr * 2;
                mk0[nf] = __ldg(reinterpret_cast<const float2*>(maskb + (size_t)tr0 * T_LEN + scol));
                mk1[nf] = __ldg(reinterpret_cast<const float2*>(maskb + (size_t)tr1 * T_LEN + scol));
            }
        }
        if (blk + 1 < NBLK) {
            load_kv_stage(blk + 1);
            cp_commit();
            cp_wait<1>();
        } else {
            cp_wait<0>();
        }
        __syncthreads();

        if (blk == 0) {
#pragma unroll
            for (int ks = 0; ks < 4; ks++) {
                uint32_t aoff = sw128((uint32_t)(wr0 + (lane & 15)) * 128 +
                                      (uint32_t)(ks * 16 + (lane >> 4) * 8) * 2);
                ldm_x4(qfh[ks], sb + AQ_H + aoff);
            }
        }

        const uint32_t B = sb + AST0 + (uint32_t)(blk & 1) * AST_STRIDE;

        // ---- S2 = (Q*log2e) K ----
        float S[8][4];
#pragma unroll
        for (int i = 0; i < 8; i++)
#pragma unroll
            for (int q = 0; q < 4; q++) S[i][q] = 0.f;
#pragma unroll
        for (int ks = 0; ks < 4; ks++) {
#pragma unroll
            for (int nfp = 0; nfp < 4; nfp++) {
                uint32_t boff = sw128((uint32_t)((2 * nfp + k_nf_off) * 8 + k_row) * 128 +
                                      (uint32_t)(ks * 16 + k_k8) * 2);
                uint32_t kh[4];
                ldm_x4(kh, B + S_KH + boff);
                mma16816(S[2 * nfp + 0], qfh[ks], kh);
                mma16816(S[2 * nfp + 1], qfh[ks], kh + 2);
            }
        }

        // ---- S2 += (mask_b + bias)*log2e ; row max (in log2 units) ----
        const float* bias_s = (const float*)(smc + AST0 + (size_t)(blk & 1) * AST_STRIDE + S_BIAS);
        float rmax0 = -1e30f, rmax1 = -1e30f;
#pragma unroll
        for (int nf = 0; nf < 8; nf++) {
            const int sloc = nf * 8 + qr * 2;
            float2 ba = *reinterpret_cast<const float2*>(bias_s + (size_t)tl0 * BIAS_ST + sloc);
            float2 bb = *reinterpret_cast<const float2*>(bias_s + (size_t)(tl0 + 8) * BIAS_ST + sloc);
            S[nf][0] = fmaf(mk0[nf].x + ba.x, LOG2E, S[nf][0]);
            S[nf][1] = fmaf(mk0[nf].y + ba.y, LOG2E, S[nf][1]);
            S[nf][2] = fmaf(mk1[nf].x + bb.x, LOG2E, S[nf][2]);
            S[nf][3] = fmaf(mk1[nf].y + bb.y, LOG2E, S[nf][3]);
            rmax0 = fmaxf(rmax0, fmaxf(S[nf][0], S[nf][1]));
            rmax1 = fmaxf(rmax1, fmaxf(S[nf][2], S[nf][3]));
        }
        rmax0 = fmaxf(rmax0, __shfl_xor_sync(0xffffffffu, rmax0, 1));
        rmax0 = fmaxf(rmax0, __shfl_xor_sync(0xffffffffu, rmax0, 2));
        rmax1 = fmaxf(rmax1, __shfl_xor_sync(0xffffffffu, rmax1, 1));
        rmax1 = fmaxf(rmax1, __shfl_xor_sync(0xffffffffu, rmax1, 2));

        const float mn0 = fmaxf(m0, rmax0), mn1 = fmaxf(m1, rmax1);
        const float es0 = ex2f(m0 - mn0), es1 = ex2f(m1 - mn1);
        m0 = mn0; m1 = mn1;

        float rs0 = 0.f, rs1 = 0.f;
#pragma unroll
        for (int nf = 0; nf < 8; nf++) {
            S[nf][0] = ex2f(S[nf][0] - mn0);
            S[nf][1] = ex2f(S[nf][1] - mn0);
            S[nf][2] = ex2f(S[nf][2] - mn1);
            S[nf][3] = ex2f(S[nf][3] - mn1);
            rs0 += S[nf][0] + S[nf][1];
            rs1 += S[nf][2] + S[nf][3];
        }
        rs0 += __shfl_xor_sync(0xffffffffu, rs0, 1);
        rs0 += __shfl_xor_sync(0xffffffffu, rs0, 2);
        rs1 += __shfl_xor_sync(0xffffffffu, rs1, 1);
        rs1 += __shfl_xor_sync(0xffffffffu, rs1, 2);
        l0 = l0 * es0 + rs0;
        l1 = l1 * es1 + rs1;

#pragma unroll
        for (int i = 0; i < 8; i++) {
            O[i][0] *= es0; O[i][1] *= es0;
            O[i][2] *= es1; O[i][3] *= es1;
        }

        // ---- O += Ph Vh ----
#pragma unroll
        for (int kp = 0; kp < 4; kp++) {
            uint32_t ah[4];
            ah[0] = pack_hi2(S[2*kp][0],   S[2*kp][1]);
            ah[1] = pack_hi2(S[2*kp][2],   S[2*kp][3]);
            ah[2] = pack_hi2(S[2*kp+1][0], S[2*kp+1][1]);
            ah[3] = pack_hi2(S[2*kp+1][2], S[2*kp+1][3]);
#pragma unroll
            for (int np = 0; np < 4; np++) {
                uint32_t voff = sw128((uint32_t)(kp * 16 + v_row) * 128 +
                                      (uint32_t)(2 * np + v_blk) * 16);
                uint32_t vh[4];
                ldm_x4_trans(vh, B + S_VH + voff);
                mma16816(O[2 * np + 0], ah, vh);
                mma16816(O[2 * np + 1], ah, vh + 2);
            }
        }
        __syncthreads();
    }

    // ---- normalize + write fp16 hi ----
    const float inv0 = 1.f / l0, inv1 = 1.f / l1;
    const size_t base0 = ((size_t)tr0 * BSZ + b) * EMBED + h * 64;
    const size_t base1 = ((size_t)tr1 * BSZ + b) * EMBED + h * 64;
#pragma unroll
    for (int nf2 = 0; nf2 < 8; nf2++) {
        const int d0 = nf2 * 8 + qr * 2;
        float v0 = O[nf2][0] * inv0, v1 = O[nf2][1] * inv0;
        float w0 = O[nf2][2] * inv1, w1 = O[nf2][3] * inv1;
        *reinterpret_cast<uint32_t*>(g_attnh + base0 + d0) = pack_hi2(v0, v1);
        *reinterpret_cast<uint32_t*>(g_attnh + base1 + d0) = pack_hi2(w0, w1);
    }
}

// ---------------------------------------------------------------------------
extern "C" void kernel_launch(void* const* d_in, const int* in_sizes, int n_in,
                              void* d_out, int out_size)
{
    const float* query     = (const float*)d_in[0];
    const int*   kpm       = (const int*)  d_in[1];
    const float* attn_mask = (const float*)d_in[2];
    const float* attn_bias = (const float*)d_in[3];
    const float* W_in      = (const float*)d_in[4];
    const float* b_in      = (const float*)d_in[5];
    const float* W_out     = (const float*)d_in[6];
    const float* b_out     = (const float*)d_in[7];
    float*       out       = (float*)d_out;

    static bool attr_set = false;
    if (!attr_set) {
        cudaFuncSetAttribute(gemm_mma, cudaFuncAttributeMaxDynamicSharedMemorySize, GEMM_SMEM);
        cudaFuncSetAttribute(attn_mma_kernel, cudaFuncAttributeMaxDynamicSharedMemorySize, ATTN_SMEM);
        attr_set = true;
    }

    __half *Ah, *Bh, *Bl, *ATh;
    cudaGetSymbolAddress((void**)&Ah, g_Ah);
    cudaGetSymbolAddress((void**)&Bh, g_Bh);
    cudaGetSymbolAddress((void**)&Bl, g_Bl);
    cudaGetSymbolAddress((void**)&ATh, g_attnh);

    // 1) prep: query hi-only split, W_in hi/lo split, mask+kpm fold
    split_hi_kernel<<<MROWS * EMBED / 4 / 256, 256>>>(query, Ah, MROWS * EMBED / 4);
    split_kernel<<<3 * EMBED * EMBED / 4 / 256, 256>>>(W_in, Bh, Bl, 3 * EMBED * EMBED / 4);
    prep_mask_kernel<<<BSZ * T_LEN * T_LEN / 4 / 256, 256>>>(attn_mask, kpm);

    // 2) QKV projection -> fp16 q(scaled by 0.125*log2e)/k/v
    {
        dim3 grid(3 * EMBED / TN, MROWS / TM);   // (24, 32)
        gemm_mma<<<grid, 256, GEMM_SMEM>>>(Ah, Bh, Bl, b_in, 0, nullptr);
    }

    // 3) Flash attention -> fp16 attn (hi)
    {
        dim3 grid(T_LEN / ABT, NBH);   // (8, 64)
        attn_mma_kernel<<<grid, 256, ATTN_SMEM>>>(attn_bias);
    }

    // 4) split W_out; output projection (A = attn fp16 hi)
    split_kernel<<<EMBED * EMBED / 4 / 256, 256>>>(W_out, Bh, Bl, EMBED * EMBED / 4);
    {
        dim3 grid(EMBED / TN, MROWS / TM);       // (8, 32)
        gemm_mma<<<grid, 256, GEMM_SMEM>>>(ATh, Bh, Bl, b_out, 1, out);
    }
}

// round 13
// speedup vs baseline: 2.9477x; 1.2610x over previous
#include <cuda_runtime.h>
#include <cuda_fp16.h>
#include <cstdint>

// Problem constants
#define T_LEN   1024
#define BSZ     4
#define EMBED   1024
#define NHEADS  16
#define HDIM    64
#define NBH     (BSZ * NHEADS)      // 64
#define MROWS   (T_LEN * BSZ)       // 4096
#define SCALING 0.125f
#define LOG2E   1.4426950408889634f

// fp16 scratch (hi only); q carries SCALING*LOG2E
__device__ __half g_qh[NBH * T_LEN * HDIM];
__device__ __half g_kh[NBH * T_LEN * HDIM];
__device__ __half g_vh[NBH * T_LEN * HDIM];
__device__ __half g_attnh[MROWS * EMBED];
// fp16 GEMM operands (hi only)
__device__ __half g_Ah[MROWS * EMBED];
__device__ __half g_Bh[3 * EMBED * EMBED];
// mask + key-padding folded, per batch: (B, T, S)
__device__ float g_maskb[BSZ * T_LEN * T_LEN];   // 16 MB

// ---------------------------------------------------------------------------
// PTX helpers
// ---------------------------------------------------------------------------
__device__ __forceinline__ uint32_t s2u(const void* p) {
    return (uint32_t)__cvta_generic_to_shared(p);
}
__device__ __forceinline__ void cp_async16(uint32_t dst, const void* src) {
    asm volatile("cp.async.cg.shared.global [%0], [%1], 16;\n" :: "r"(dst), "l"(src));
}
__device__ __forceinline__ void cp_commit() {
    asm volatile("cp.async.commit_group;\n");
}
template<int N>
__device__ __forceinline__ void cp_wait() {
    asm volatile("cp.async.wait_group %0;\n" :: "n"(N));
}
__device__ __forceinline__ void ldm_x4(uint32_t* r, uint32_t addr) {
    asm volatile("ldmatrix.sync.aligned.m8n8.x4.shared.b16 {%0,%1,%2,%3}, [%4];"
                 : "=r"(r[0]), "=r"(r[1]), "=r"(r[2]), "=r"(r[3]) : "r"(addr));
}
__device__ __forceinline__ void ldm_x4_trans(uint32_t* r, uint32_t addr) {
    asm volatile("ldmatrix.sync.aligned.m8n8.x4.trans.shared.b16 {%0,%1,%2,%3}, [%4];"
                 : "=r"(r[0]), "=r"(r[1]), "=r"(r[2]), "=r"(r[3]) : "r"(addr));
}
__device__ __forceinline__ void mma16816(float* c, const uint32_t* a, const uint32_t* b) {
    asm volatile("mma.sync.aligned.m16n8k16.row.col.f32.f16.f16.f32 "
                 "{%0,%1,%2,%3}, {%4,%5,%6,%7}, {%8,%9}, {%0,%1,%2,%3};"
                 : "+f"(c[0]), "+f"(c[1]), "+f"(c[2]), "+f"(c[3])
                 : "r"(a[0]), "r"(a[1]), "r"(a[2]), "r"(a[3]), "r"(b[0]), "r"(b[1]));
}
__device__ __forceinline__ float ex2f(float x) {
    float y;
    asm("ex2.approx.ftz.f32 %0, %1;" : "=f"(y) : "f"(x));
    return y;
}
__device__ __host__ __forceinline__ uint32_t sw128(uint32_t off) {
    return off ^ ((off >> 3) & 0x70);
}
__device__ __forceinline__ uint32_t pack_hi2(float a, float b) {
    __half2 t; t.x = __float2half_rn(a); t.y = __float2half_rn(b);
    uint32_t r; memcpy(&r, &t, 4); return r;
}

// ---------------------------------------------------------------------------
// Prep kernels
// ---------------------------------------------------------------------------
__global__ __launch_bounds__(256)
void split_hi_kernel(const float* __restrict__ src, __half* __restrict__ hi, int n4)
{
    int i = blockIdx.x * 256 + threadIdx.x;
    if (i >= n4) return;
    float4 v = reinterpret_cast<const float4*>(src)[i];
    reinterpret_cast<uint32_t*>(hi)[2 * i]     = pack_hi2(v.x, v.y);
    reinterpret_cast<uint32_t*>(hi)[2 * i + 1] = pack_hi2(v.z, v.w);
}

// mask_b[b][t][s] = mask[t][s] + (kpm[b][s] ? -1e30 : 0)
__global__ __launch_bounds__(256)
void prep_mask_kernel(const float* __restrict__ mask, const int* __restrict__ kpm)
{
    int i = blockIdx.x * 256 + threadIdx.x;        // over BSZ*T*T/4
    int idx = i * 4;
    int b = idx >> 20;
    int rem = idx & ((1 << 20) - 1);
    int t = rem >> 10;
    int s = rem & 1023;
    float4 m = *reinterpret_cast<const float4*>(mask + (size_t)t * T_LEN + s);
    const int* kp = kpm + b * T_LEN + s;
    float4 o;
    o.x = m.x + (kp[0] ? -1e30f : 0.f);
    o.y = m.y + (kp[1] ? -1e30f : 0.f);
    o.z = m.z + (kp[2] ? -1e30f : 0.f);
    o.w = m.w + (kp[3] ? -1e30f : 0.f);
    reinterpret_cast<float4*>(g_maskb)[i] = o;
}

// ---------------------------------------------------------------------------
// mma.sync fp16 single-product GEMM: D = Ah*Bh. 2 CTAs/SM.
// 256 threads, 8 warps x (64x32), 2-stage cp.async (40KB smem).
// ---------------------------------------------------------------------------
#define GK 1024
#define TM 128
#define TN 128
#define TBK 32
#define NKS (GK / TBK)
#define A_ST 40
#define TILE_B (128 * A_ST * 2)     // 10240
#define STAGE_B (2 * TILE_B)        // Ah, Bh
#define GEMM_SMEM (2 * STAGE_B)     // 40960

__device__ __forceinline__ void load_stage(uint32_t sbase,
    const __half* __restrict__ Ah, const __half* __restrict__ Bh,
    int row0, int col0, int k0, int tid)
{
#pragma unroll
    for (int it = 0; it < 2; it++) {
        int idx = it * 256 + tid;
        int r = idx >> 2, c = idx & 3;
        uint32_t so = r * (A_ST * 2) + c * 16;
        size_t ga = (size_t)(row0 + r) * GK + k0 + c * 8;
        size_t gb = (size_t)(col0 + r) * GK + k0 + c * 8;
        cp_async16(sbase + 0 * TILE_B + so, Ah + ga);
        cp_async16(sbase + 1 * TILE_B + so, Bh + gb);
    }
}

__global__ __launch_bounds__(256, 2)
void gemm_mma(const __half* __restrict__ Ah, const __half* __restrict__ Bh,
              const float* __restrict__ bias, int mode, float* __restrict__ out)
{
    extern __shared__ char smc[];
    const uint32_t sb = s2u(smc);
    const int tid  = threadIdx.x;
    const int lane = tid & 31;
    const int wid  = tid >> 5;
    const int wr = wid & 1;
    const int wc = wid >> 1;
    const int row0 = blockIdx.y * TM, col0 = blockIdx.x * TN;

    const int a_row = lane & 15;
    const int a_k8  = (lane >> 4) * 8;
    const int b_mat = lane >> 3;
    const int b_nf_off = b_mat >> 1;
    const int b_k8  = (b_mat & 1) * 8;
    const int b_row = lane & 7;

    float acc[4][4][4];
#pragma unroll
    for (int i = 0; i < 4; i++)
#pragma unroll
        for (int j = 0; j < 4; j++)
#pragma unroll
            for (int q = 0; q < 4; q++) acc[i][j][q] = 0.f;

    load_stage(sb, Ah, Bh, row0, col0, 0, tid);
    cp_commit();

    for (int ks = 0; ks < NKS; ks++) {
        const uint32_t cur = sb + (uint32_t)(ks & 1) * STAGE_B;
        if (ks + 1 < NKS) {
            load_stage(sb + (uint32_t)((ks + 1) & 1) * STAGE_B,
                       Ah, Bh, row0, col0, (ks + 1) * TBK, tid);
            cp_commit();
            cp_wait<1>();
        } else {
            cp_wait<0>();
        }
        __syncthreads();

#pragma unroll
        for (int kk = 0; kk < 2; kk++) {
            const int k0 = kk * 16;
            uint32_t afh[4][4];
#pragma unroll
            for (int mf = 0; mf < 4; mf++) {
                uint32_t aoff = (uint32_t)((wr * 64 + mf * 16 + a_row) * A_ST + k0 + a_k8) * 2;
                ldm_x4(afh[mf], cur + 0 * TILE_B + aoff);
            }
            uint32_t bfh[2][4];
#pragma unroll
            for (int nfp = 0; nfp < 2; nfp++) {
                uint32_t boff = (uint32_t)((wc * 32 + (2 * nfp + b_nf_off) * 8 + b_row) * A_ST
                                           + k0 + b_k8) * 2;
                ldm_x4(bfh[nfp], cur + 1 * TILE_B + boff);
            }
#pragma unroll
            for (int mf = 0; mf < 4; mf++)
#pragma unroll
                for (int nfp = 0; nfp < 2; nfp++)
#pragma unroll
                    for (int half = 0; half < 2; half++) {
                        const int nf = 2 * nfp + half;
                        mma16816(acc[mf][nf], afh[mf], bfh[nfp] + half * 2);
                    }
        }
        __syncthreads();
    }

    const int g = lane >> 2, tig = lane & 3;
#pragma unroll
    for (int nf = 0; nf < 4; nf++) {
        const int e = col0 + wc * 32 + nf * 8 + tig * 2;
        const float bz0 = __ldg(bias + e);
        const float bz1 = __ldg(bias + e + 1);
#pragma unroll
        for (int mf = 0; mf < 4; mf++) {
#pragma unroll
            for (int half = 0; half < 2; half++) {
                const int m = row0 + wr * 64 + mf * 16 + g + half * 8;
                float v0 = acc[mf][nf][half * 2 + 0] + bz0;
                float v1 = acc[mf][nf][half * 2 + 1] + bz1;
                if (mode == 0) {
                    const int t = m >> 2, b = m & 3;
                    const int which = e >> 10;
                    const int rem = e & 1023;
                    const int h = rem >> 6, d = rem & 63;
                    const int n = (b << 4) + h;
                    size_t off = ((size_t)n << 16) + ((size_t)t << 6) + d;
                    if (which == 0) {
                        const float qs = SCALING * LOG2E;   // exp2-form softmax
                        v0 *= qs; v1 *= qs;
                    }
                    __half* dh = (which == 0) ? g_qh : (which == 1) ? g_kh : g_vh;
                    *reinterpret_cast<uint32_t*>(dh + off) = pack_hi2(v0, v1);
                } else {
                    *reinterpret_cast<float2*>(out + (size_t)m * EMBED + e)
                        = make_float2(v0, v1);
                }
            }
        }
    }
}

// ---------------------------------------------------------------------------
// Flash attention — exp2 softmax, mask_b (kpm folded), single-product fp16.
// (unchanged from R12)
// ---------------------------------------------------------------------------
#define ABT 128
#define ABS 64
#define NBLK (T_LEN / ABS)   // 16
#define AQ_H   0
#define AST0   16384
#define S_KH    0
#define S_VH    8192
#define S_BIAS  16384
#define BIAS_ST 68
#define AST_STRIDE (16384 + 128 * BIAS_ST * 4)   // 51200
#define ATTN_SMEM (AST0 + 2 * AST_STRIDE)        // 118784

__global__ __launch_bounds__(256, 1)
void attn_mma_kernel(const float* __restrict__ attn_bias)
{
    extern __shared__ char smc[];
    const uint32_t sb = s2u(smc);
    const int tid = threadIdx.x, lane = tid & 31, wid = tid >> 5;
    const int n = blockIdx.y, t0 = blockIdx.x * ABT;
    const int b = n >> 4, h = n & 15;
    const int wr0 = wid * 16;
    const int g = lane >> 2, qr = lane & 3;
    const size_t nbase = (size_t)n << 16;
    const float* biasg = attn_bias + (size_t)n * T_LEN * T_LEN;
    const float* maskb = g_maskb + (size_t)b * T_LEN * T_LEN;

    auto load_kv_stage = [&](int blk) {
        const int s0 = blk * ABS;
        const uint32_t B = sb + AST0 + (uint32_t)(blk & 1) * AST_STRIDE;
#pragma unroll
        for (int it = 0; it < 2; it++) {
            int idx = it * 256 + tid;
            int row = idx >> 3, c = idx & 7;
            uint32_t so = sw128(row * 128 + c * 16);
            size_t go = nbase + (size_t)(s0 + row) * 64 + c * 8;
            cp_async16(B + S_KH + so, g_kh + go);
            cp_async16(B + S_VH + so, g_vh + go);
        }
#pragma unroll
        for (int it = 0; it < 8; it++) {
            int idx = it * 256 + tid;
            int row = idx >> 4, c = idx & 15;
            cp_async16(B + S_BIAS + row * (BIAS_ST * 4) + c * 16,
                       biasg + (size_t)(t0 + row) * T_LEN + s0 + c * 4);
        }
    };

    // --- prologue: Q(hi, pre-scaled by 0.125*log2e) + stage 0 ---
    {
        const __half* Qh = g_qh + nbase + (size_t)t0 * 64;
#pragma unroll
        for (int it = 0; it < 4; it++) {
            int idx = it * 256 + tid;
            int row = idx >> 3, c = idx & 7;
            uint32_t so = sw128(row * 128 + c * 16);
            cp_async16(sb + AQ_H + so, Qh + row * 64 + c * 8);
        }
        load_kv_stage(0);
        cp_commit();
    }

    float m0 = -1e30f, m1 = -1e30f, l0 = 0.f, l1 = 0.f;
    float O[8][4];
#pragma unroll
    for (int i = 0; i < 8; i++)
#pragma unroll
        for (int q = 0; q < 4; q++) O[i][q] = 0.f;
    uint32_t qfh[4][4];

    const int tr0 = t0 + wr0 + g, tr1 = tr0 + 8;
    const int tl0 = wr0 + g;

    const int k_mat = lane >> 3;
    const int k_nf_off = k_mat >> 1;
    const int k_k8 = (k_mat & 1) * 8;
    const int k_row = lane & 7;
    const int v_blk = lane >> 4;
    const int v_row = lane & 15;

    for (int blk = 0; blk < NBLK; blk++) {
        // mask_b prefetch to regs (kpm already folded in)
        float2 mk0[8], mk1[8];
        {
            const int s0g = blk * ABS;
#pragma unroll
            for (int nf = 0; nf < 8; nf++) {
                const int scol = s0g + nf * 8 + qr * 2;
                mk0[nf] = __ldg(reinterpret_cast<const float2*>(maskb + (size_t)tr0 * T_LEN + scol));
                mk1[nf] = __ldg(reinterpret_cast<const float2*>(maskb + (size_t)tr1 * T_LEN + scol));
            }
        }
        if (blk + 1 < NBLK) {
            load_kv_stage(blk + 1);
            cp_commit();
            cp_wait<1>();
        } else {
            cp_wait<0>();
        }
        __syncthreads();

        if (blk == 0) {
#pragma unroll
            for (int ks = 0; ks < 4; ks++) {
                uint32_t aoff = sw128((uint32_t)(wr0 + (lane & 15)) * 128 +
                                      (uint32_t)(ks * 16 + (lane >> 4) * 8) * 2);
                ldm_x4(qfh[ks], sb + AQ_H + aoff);
            }
        }

        const uint32_t B = sb + AST0 + (uint32_t)(blk & 1) * AST_STRIDE;

        // ---- S2 = (Q*log2e) K ----
        float S[8][4];
#pragma unroll
        for (int i = 0; i < 8; i++)
#pragma unroll
            for (int q = 0; q < 4; q++) S[i][q] = 0.f;
#pragma unroll
        for (int ks = 0; ks < 4; ks++) {
#pragma unroll
            for (int nfp = 0; nfp < 4; nfp++) {
                uint32_t boff = sw128((uint32_t)((2 * nfp + k_nf_off) * 8 + k_row) * 128 +
                                      (uint32_t)(ks * 16 + k_k8) * 2);
                uint32_t kh[4];
                ldm_x4(kh, B + S_KH + boff);
                mma16816(S[2 * nfp + 0], qfh[ks], kh);
                mma16816(S[2 * nfp + 1], qfh[ks], kh + 2);
            }
        }

        // ---- S2 += (mask_b + bias)*log2e ; row max (in log2 units) ----
        const float* bias_s = (const float*)(smc + AST0 + (size_t)(blk & 1) * AST_STRIDE + S_BIAS);
        float rmax0 = -1e30f, rmax1 = -1e30f;
#pragma unroll
        for (int nf = 0; nf < 8; nf++) {
            const int sloc = nf * 8 + qr * 2;
            float2 ba = *reinterpret_cast<const float2*>(bias_s + (size_t)tl0 * BIAS_ST + sloc);
            float2 bb = *reinterpret_cast<const float2*>(bias_s + (size_t)(tl0 + 8) * BIAS_ST + sloc);
            S[nf][0] = fmaf(mk0[nf].x + ba.x, LOG2E, S[nf][0]);
            S[nf][1] = fmaf(mk0[nf].y + ba.y, LOG2E, S[nf][1]);
            S[nf][2] = fmaf(mk1[nf].x + bb.x, LOG2E, S[nf][2]);
            S[nf][3] = fmaf(mk1[nf].y + bb.y, LOG2E, S[nf][3]);
            rmax0 = fmaxf(rmax0, fmaxf(S[nf][0], S[nf][1]));
            rmax1 = fmaxf(rmax1, fmaxf(S[nf][2], S[nf][3]));
        }
        rmax0 = fmaxf(rmax0, __shfl_xor_sync(0xffffffffu, rmax0, 1));
        rmax0 = fmaxf(rmax0, __shfl_xor_sync(0xffffffffu, rmax0, 2));
        rmax1 = fmaxf(rmax1, __shfl_xor_sync(0xffffffffu, rmax1, 1));
        rmax1 = fmaxf(rmax1, __shfl_xor_sync(0xffffffffu, rmax1, 2));

        const float mn0 = fmaxf(m0, rmax0), mn1 = fmaxf(m1, rmax1);
        const float es0 = ex2f(m0 - mn0), es1 = ex2f(m1 - mn1);
        m0 = mn0; m1 = mn1;

        float rs0 = 0.f, rs1 = 0.f;
#pragma unroll
        for (int nf = 0; nf < 8; nf++) {
            S[nf][0] = ex2f(S[nf][0] - mn0);
            S[nf][1] = ex2f(S[nf][1] - mn0);
            S[nf][2] = ex2f(S[nf][2] - mn1);
            S[nf][3] = ex2f(S[nf][3] - mn1);
            rs0 += S[nf][0] + S[nf][1];
            rs1 += S[nf][2] + S[nf][3];
        }
        rs0 += __shfl_xor_sync(0xffffffffu, rs0, 1);
        rs0 += __shfl_xor_sync(0xffffffffu, rs0, 2);
        rs1 += __shfl_xor_sync(0xffffffffu, rs1, 1);
        rs1 += __shfl_xor_sync(0xffffffffu, rs1, 2);
        l0 = l0 * es0 + rs0;
        l1 = l1 * es1 + rs1;

#pragma unroll
        for (int i = 0; i < 8; i++) {
            O[i][0] *= es0; O[i][1] *= es0;
            O[i][2] *= es1; O[i][3] *= es1;
        }

        // ---- O += Ph Vh ----
#pragma unroll
        for (int kp = 0; kp < 4; kp++) {
            uint32_t ah[4];
            ah[0] = pack_hi2(S[2*kp][0],   S[2*kp][1]);
            ah[1] = pack_hi2(S[2*kp][2],   S[2*kp][3]);
            ah[2] = pack_hi2(S[2*kp+1][0], S[2*kp+1][1]);
            ah[3] = pack_hi2(S[2*kp+1][2], S[2*kp+1][3]);
#pragma unroll
            for (int np = 0; np < 4; np++) {
                uint32_t voff = sw128((uint32_t)(kp * 16 + v_row) * 128 +
                                      (uint32_t)(2 * np + v_blk) * 16);
                uint32_t vh[4];
                ldm_x4_trans(vh, B + S_VH + voff);
                mma16816(O[2 * np + 0], ah, vh);
                mma16816(O[2 * np + 1], ah, vh + 2);
            }
        }
        __syncthreads();
    }

    // ---- normalize + write fp16 hi ----
    const float inv0 = 1.f / l0, inv1 = 1.f / l1;
    const size_t base0 = ((size_t)tr0 * BSZ + b) * EMBED + h * 64;
    const size_t base1 = ((size_t)tr1 * BSZ + b) * EMBED + h * 64;
#pragma unroll
    for (int nf2 = 0; nf2 < 8; nf2++) {
        const int d0 = nf2 * 8 + qr * 2;
        float v0 = O[nf2][0] * inv0, v1 = O[nf2][1] * inv0;
        float w0 = O[nf2][2] * inv1, w1 = O[nf2][3] * inv1;
        *reinterpret_cast<uint32_t*>(g_attnh + base0 + d0) = pack_hi2(v0, v1);
        *reinterpret_cast<uint32_t*>(g_attnh + base1 + d0) = pack_hi2(w0, w1);
    }
}

// ---------------------------------------------------------------------------
extern "C" void kernel_launch(void* const* d_in, const int* in_sizes, int n_in,
                              void* d_out, int out_size)
{
    const float* query     = (const float*)d_in[0];
    const int*   kpm       = (const int*)  d_in[1];
    const float* attn_mask = (const float*)d_in[2];
    const float* attn_bias = (const float*)d_in[3];
    const float* W_in      = (const float*)d_in[4];
    const float* b_in      = (const float*)d_in[5];
    const float* W_out     = (const float*)d_in[6];
    const float* b_out     = (const float*)d_in[7];
    float*       out       = (float*)d_out;

    static bool attr_set = false;
    if (!attr_set) {
        cudaFuncSetAttribute(gemm_mma, cudaFuncAttributeMaxDynamicSharedMemorySize, GEMM_SMEM);
        cudaFuncSetAttribute(attn_mma_kernel, cudaFuncAttributeMaxDynamicSharedMemorySize, ATTN_SMEM);
        attr_set = true;
    }

    __half *Ah, *Bh, *ATh;
    cudaGetSymbolAddress((void**)&Ah, g_Ah);
    cudaGetSymbolAddress((void**)&Bh, g_Bh);
    cudaGetSymbolAddress((void**)&ATh, g_attnh);

    // 1) prep: hi-only splits + mask fold
    split_hi_kernel<<<MROWS * EMBED / 4 / 256, 256>>>(query, Ah, MROWS * EMBED / 4);
    split_hi_kernel<<<3 * EMBED * EMBED / 4 / 256, 256>>>(W_in, Bh, 3 * EMBED * EMBED / 4);
    prep_mask_kernel<<<BSZ * T_LEN * T_LEN / 4 / 256, 256>>>(attn_mask, kpm);

    // 2) QKV projection -> fp16 q(scaled by 0.125*log2e)/k/v
    {
        dim3 grid(3 * EMBED / TN, MROWS / TM);   // (24, 32)
        gemm_mma<<<grid, 256, GEMM_SMEM>>>(Ah, Bh, b_in, 0, nullptr);
    }

    // 3) Flash attention -> fp16 attn (hi)
    {
        dim3 grid(T_LEN / ABT, NBH);   // (8, 64)
        attn_mma_kernel<<<grid, 256, ATTN_SMEM>>>(attn_bias);
    }

    // 4) split W_out (hi); output projection (A = attn fp16 hi)
    split_hi_kernel<<<EMBED * EMBED / 4 / 256, 256>>>(W_out, Bh, EMBED * EMBED / 4);
    {
        dim3 grid(EMBED / TN, MROWS / TM);       // (8, 32)
        gemm_mma<<<grid, 256, GEMM_SMEM>>>(ATh, Bh, b_out, 1, out);
    }
}